// round 13
// baseline (speedup 1.0000x reference)
#include <cuda_runtime.h>
#include <cuda_fp16.h>
#include <cstdint>
#include <math.h>

// Problem constants
#define B_    2
#define S_    2048
#define D_    4096
#define NH    32
#define NKV   8
#define HD    128
#define MTOK  (B_*S_)          // 4096 tokens
#define KVDIM (NKV*HD)         // 1024
#define QKVN  (D_ + 2*KVDIM)   // 6144 fused projection width
#define KW    4096             // operand K width
#define QSCALE 0.08838834764831845f
#define ROPE_THETA 500000.0

// -------------------- scratch (device globals; no allocs allowed) -----------
__device__ float   g_cos[2048 * 64];
__device__ float   g_sin[2048 * 64];
__device__ __half  g_Xh [(size_t)MTOK * D_];      // x hi (fp16)
__device__ uint8_t g_Xl8[(size_t)MTOK * D_];      // x lo (e5m2)
__device__ __half  g_Qh [(size_t)MTOK * D_];      // q hi (fp16, scaled+rope)
__device__ __half  g_Ql [(size_t)MTOK * D_];      // q lo (fp16, for flash)
__device__ __half  g_Kh [(size_t)MTOK * KVDIM];
__device__ __half  g_Vh [(size_t)MTOK * KVDIM];
__device__ __half  g_Oh [(size_t)MTOK * D_];      // attn out hi (fp16)
__device__ uint8_t g_Ol8[(size_t)MTOK * D_];      // attn out lo (e5m2)
__device__ __half  g_Wh [(size_t)10240 * KW];     // weights fp16: qkv | wo
__device__ uint8_t g_W8 [(size_t)10240 * KW];     // weights e4m3: qkv | wo

// =====================  PTX helpers (baseline ISA only)  ====================
__device__ __forceinline__ uint32_t smem_u32(const void* p) {
    uint32_t a;
    asm("{ .reg .u64 t; cvta.to.shared.u64 t, %1; cvt.u32.u64 %0, t; }" : "=r"(a) : "l"(p));
    return a;
}
__device__ __forceinline__ void cp_async16(uint32_t s, const void* g) {
    asm volatile("cp.async.cg.shared.global [%0], [%1], 16;" :: "r"(s), "l"(g));
}
__device__ __forceinline__ void cp_commit() {
    asm volatile("cp.async.commit_group;" ::: "memory");
}
template<int N_> __device__ __forceinline__ void cp_wait() {
    asm volatile("cp.async.wait_group %0;" :: "n"(N_) : "memory");
}
__device__ __forceinline__ void ldmatrix_x4(uint32_t* r, uint32_t addr) {
    asm volatile("ldmatrix.sync.aligned.m8n8.x4.shared.b16 {%0,%1,%2,%3}, [%4];"
                 : "=r"(r[0]), "=r"(r[1]), "=r"(r[2]), "=r"(r[3]) : "r"(addr));
}
__device__ __forceinline__ void ldmatrix_x4_trans(uint32_t* r, uint32_t addr) {
    asm volatile("ldmatrix.sync.aligned.m8n8.x4.trans.shared.b16 {%0,%1,%2,%3}, [%4];"
                 : "=r"(r[0]), "=r"(r[1]), "=r"(r[2]), "=r"(r[3]) : "r"(addr));
}
__device__ __forceinline__ void mma_16816(float* d, const uint32_t* a, const uint32_t* b) {
    asm volatile(
        "mma.sync.aligned.m16n8k16.row.col.f32.f16.f16.f32 "
        "{%0,%1,%2,%3}, {%4,%5,%6,%7}, {%8,%9}, {%0,%1,%2,%3};"
        : "+f"(d[0]), "+f"(d[1]), "+f"(d[2]), "+f"(d[3])
        : "r"(a[0]), "r"(a[1]), "r"(a[2]), "r"(a[3]), "r"(b[0]), "r"(b[1]));
}
// FP8 lo-term MMA: A = e5m2, B = e4m3, k32
__device__ __forceinline__ void mma_fp8(float* d, const uint32_t* a, const uint32_t* b) {
    asm volatile(
        "mma.sync.aligned.m16n8k32.row.col.f32.e5m2.e4m3.f32 "
        "{%0,%1,%2,%3}, {%4,%5,%6,%7}, {%8,%9}, {%0,%1,%2,%3};"
        : "+f"(d[0]), "+f"(d[1]), "+f"(d[2]), "+f"(d[3])
        : "r"(a[0]), "r"(a[1]), "r"(a[2]), "r"(a[3]), "r"(b[0]), "r"(b[1]));
}
__device__ __forceinline__ uint32_t pk_f16x2(float lo, float hi) {
    uint32_t d;
    asm("cvt.rn.f16x2.f32 %0, %1, %2;" : "=r"(d) : "f"(hi), "f"(lo));
    return d;
}
__device__ __forceinline__ float2 unpk_f16x2(uint32_t u) {
    __half2 h = *(__half2*)&u;
    return __half22float2(h);
}
__device__ __forceinline__ uint16_t pk_e5m2x2(float lo, float hi) {
    uint16_t d;
    asm("cvt.rn.satfinite.e5m2x2.f32 %0, %1, %2;" : "=h"(d) : "f"(hi), "f"(lo));
    return d;
}
__device__ __forceinline__ uint8_t to_e4m3(float v) {
    uint16_t d;
    asm("cvt.rn.satfinite.e4m3x2.f32 %0, %1, %2;" : "=h"(d) : "f"(0.f), "f"(v));
    return (uint8_t)(d & 0xff);
}

// =====================  conversion kernels  =================================
// X[4096][4096] fp32 -> Xh fp16 + Xl8 e5m2 (exact hi + fp8 lo)
__global__ __launch_bounds__(256) void convert_a_kernel(const float* __restrict__ X,
                                                        __half* __restrict__ Yh,
                                                        uint8_t* __restrict__ Yl8) {
    int i = blockIdx.x * blockDim.x + threadIdx.x;
    int row = i >> 10;
    int col = (i & 1023) << 2;
    float4 v = ((const float4*)X)[i];
    __half hx = __float2half_rn(v.x);
    __half hy = __float2half_rn(v.y);
    __half hz = __float2half_rn(v.z);
    __half hw = __float2half_rn(v.w);
    float lx = v.x - __half2float(hx);
    float ly = v.y - __half2float(hy);
    float lz = v.z - __half2float(hz);
    float lw = v.w - __half2float(hw);
    size_t base = (size_t)row * KW + col;
    ((__half2*)(Yh + base))[0] = __halves2half2(hx, hy);
    ((__half2*)(Yh + base))[1] = __halves2half2(hz, hw);
    uint32_t p = (uint32_t)pk_e5m2x2(lx, ly) | ((uint32_t)pk_e5m2x2(lz, lw) << 16);
    *(uint32_t*)(Yl8 + base) = p;
}

// W[K=4096][N] fp32 -> Yh fp16 + Y8 e4m3, transposed to [N][KW]
__global__ __launch_bounds__(256) void convert_w_kernel(const float* __restrict__ W,
                                                        __half* __restrict__ Yh,
                                                        uint8_t* __restrict__ Y8, int N) {
    __shared__ float t[32][33];
    int n0 = blockIdx.x * 32;
    int k0 = blockIdx.y * 32;
    int tx = threadIdx.x;
    int ty = threadIdx.y;
#pragma unroll
    for (int i = 0; i < 4; i++)
        t[ty + 8 * i][tx] = W[(size_t)(k0 + ty + 8 * i) * N + n0 + tx];
    __syncthreads();
#pragma unroll
    for (int i = 0; i < 4; i++) {
        int r = ty + 8 * i;
        float v = t[tx][r];
        size_t o = (size_t)(n0 + r) * KW + k0 + tx;
        Yh[o] = __float2half_rn(v);
        Y8[o] = to_e4m3(v);
    }
}

// =====================  RoPE table  =========================================
__global__ void rope_table_kernel() {
    int idx = blockIdx.x * blockDim.x + threadIdx.x;
    if (idx >= 2048 * 64) return;
    int p = idx >> 6;
    int i = idx & 63;
    double inv_d = exp(-((double)(2 * i) / (double)HD) * log(ROPE_THETA));
    float invf = (float)inv_d;
    float angf = (float)p * invf;
    g_cos[idx] = (float)cos((double)angf);
    g_sin[idx] = (float)sin((double)angf);
}

// =====================  mma.sync split GEMM (fp16 hi + fp8 lo)  =============
// CTA 128x128, 256 threads (8 warps, 2x4), warp tile 64x32, BK=64, 2 stages.
// Stage: Ah 16KB | Al8 8KB | B 16KB | B8 8KB = 48KB.
// C = Ah*B (fp16 mma) + Al8*B8 (fp8 mma), accumulated fp32.
#define BKK 64
#define NST 2
#define STAGE_BYTES 49152
#define GEMM_SMEM (NST * STAGE_BYTES)
#define OFF_AL8 16384u
#define OFF_B   24576u
#define OFF_B8  40960u

__device__ __forceinline__ void gemm_load_stage(
    const __half* __restrict__ A, const uint8_t* __restrict__ A8,
    const __half* __restrict__ Bt, const uint8_t* __restrict__ Bt8,
    int m0, int n0, int it, uint32_t st, int tid)
{
    int kk = it * BKK;
#pragma unroll
    for (int u = 0; u < 4; u++) {             // A-hi fp16: 128 rows x 128B
        int f = u * 256 + tid;
        int r = f >> 3;
        int c = f & 7;
        uint32_t sw = (uint32_t)(c ^ (r & 7));
        cp_async16(st + (uint32_t)r * 128u + sw * 16u,
                   A + (size_t)(m0 + r) * KW + kk + c * 8);
    }
#pragma unroll
    for (int u = 0; u < 2; u++) {             // A-lo fp8: 128 rows x 64B
        int f = u * 256 + tid;
        int r = f >> 2;
        int c = f & 3;
        uint32_t sw = (uint32_t)(c ^ ((r >> 1) & 3));
        cp_async16(st + OFF_AL8 + (uint32_t)r * 64u + sw * 16u,
                   A8 + (size_t)(m0 + r) * KW + kk + c * 16);
    }
#pragma unroll
    for (int u = 0; u < 4; u++) {             // B fp16: 128 rows x 128B
        int f = u * 256 + tid;
        int r = f >> 3;
        int c = f & 7;
        uint32_t sw = (uint32_t)(c ^ (r & 7));
        cp_async16(st + OFF_B + (uint32_t)r * 128u + sw * 16u,
                   Bt + (size_t)(n0 + r) * KW + kk + c * 8);
    }
#pragma unroll
    for (int u = 0; u < 2; u++) {             // B fp8: 128 rows x 64B
        int f = u * 256 + tid;
        int r = f >> 2;
        int c = f & 3;
        uint32_t sw = (uint32_t)(c ^ ((r >> 1) & 3));
        cp_async16(st + OFF_B8 + (uint32_t)r * 64u + sw * 16u,
                   Bt8 + (size_t)(n0 + r) * KW + kk + c * 16);
    }
    cp_commit();
}

template<int MODE>
__global__ __launch_bounds__(256, 2) void gemm_f16_kernel(
    const __half* __restrict__ A, const uint8_t* __restrict__ A8,
    const __half* __restrict__ Bt, const uint8_t* __restrict__ Bt8,
    float* __restrict__ C, int N,
    __half* __restrict__ qh, __half* __restrict__ ql,
    __half* __restrict__ kh, __half* __restrict__ vh,
    const int* __restrict__ pos)
{
    extern __shared__ __align__(1024) char gsm[];
    const uint32_t sbase = smem_u32(gsm);
    const int tid  = threadIdx.x;
    const int wid  = tid >> 5;
    const int lane = tid & 31;

    const int m0 = blockIdx.x * 128;
    const int n0 = blockIdx.y * 128;
    const int wm = (wid >> 2) * 64;
    const int wn = (wid & 3) * 32;

    float acc[4][4][4];
#pragma unroll
    for (int i = 0; i < 4; i++)
#pragma unroll
        for (int j = 0; j < 4; j++)
#pragma unroll
            for (int e = 0; e < 4; e++) acc[i][j][e] = 0.f;

    const int iters = 64;   // 64 K-chunks of 64
    gemm_load_stage(A, A8, Bt, Bt8, m0, n0, 0, sbase + 0u * STAGE_BYTES, tid);
    gemm_load_stage(A, A8, Bt, Bt8, m0, n0, 1, sbase + 1u * STAGE_BYTES, tid);

    const int a_row_in16 = ((lane >> 3) & 1) * 8 + (lane & 7);
    const int a_cs       = lane >> 4;
    const int b_sel      = lane >> 4;
    const int b_row8     = lane & 7;
    const int b_cs       = (lane >> 3) & 1;

    for (int it = 0; it < iters; it++) {
        cp_wait<1>();
        __syncthreads();

        uint32_t st  = sbase + (uint32_t)(it & 1) * STAGE_BYTES;
        uint32_t sAh = st;
        uint32_t sA8 = st + OFF_AL8;
        uint32_t sB  = st + OFF_B;
        uint32_t sB8 = st + OFF_B8;

        // ---- hi terms: fp16 mma over 4 k16 steps ----
#pragma unroll
        for (int ks = 0; ks < 4; ks++) {
            int c0 = ks * 2;
            uint32_t bfr[2][4];
#pragma unroll
            for (int njp = 0; njp < 2; njp++) {
                int r  = wn + (njp * 2 + b_sel) * 8 + b_row8;
                int cc = c0 + b_cs;
                uint32_t addr = sB + (uint32_t)r * 128u + (uint32_t)((cc ^ (r & 7)) * 16);
                ldmatrix_x4(bfr[njp], addr);
            }
#pragma unroll
            for (int im = 0; im < 4; im++) {
                int r  = wm + im * 16 + a_row_in16;
                int cc = c0 + a_cs;
                uint32_t addr = sAh + (uint32_t)r * 128u + (uint32_t)((cc ^ (r & 7)) * 16);
                uint32_t afh[4];
                ldmatrix_x4(afh, addr);
#pragma unroll
                for (int njp = 0; njp < 2; njp++) {
                    mma_16816(acc[im][2 * njp],     afh, bfr[njp]);
                    mma_16816(acc[im][2 * njp + 1], afh, bfr[njp] + 2);
                }
            }
        }

        // ---- lo terms: fp8 mma over 2 k32 steps ----
#pragma unroll
        for (int ks8 = 0; ks8 < 2; ks8++) {
            uint32_t bfr8[2][4];
#pragma unroll
            for (int njp = 0; njp < 2; njp++) {
                int r  = wn + (njp * 2 + b_sel) * 8 + b_row8;
                int cc = 2 * ks8 + b_cs;
                uint32_t addr = sB8 + (uint32_t)r * 64u + (uint32_t)((cc ^ ((r >> 1) & 3)) * 16);
                ldmatrix_x4(bfr8[njp], addr);
            }
#pragma unroll
            for (int im = 0; im < 4; im++) {
                int r  = wm + im * 16 + a_row_in16;
                int cc = 2 * ks8 + a_cs;
                uint32_t addr = sA8 + (uint32_t)r * 64u + (uint32_t)((cc ^ ((r >> 1) & 3)) * 16);
                uint32_t afl8[4];
                ldmatrix_x4(afl8, addr);
#pragma unroll
                for (int njp = 0; njp < 2; njp++) {
                    mma_fp8(acc[im][2 * njp],     afl8, bfr8[njp]);
                    mma_fp8(acc[im][2 * njp + 1], afl8, bfr8[njp] + 2);
                }
            }
        }

        __syncthreads();
        if (it + 2 < iters)
            gemm_load_stage(A, A8, Bt, Bt8, m0, n0, it + 2, st, tid);
    }

    const int tg = lane >> 2;
    const int tc = lane & 3;

    if (MODE == 0) {
#pragma unroll
        for (int im = 0; im < 4; im++) {
#pragma unroll
            for (int jn = 0; jn < 4; jn++) {
                int row = m0 + wm + im * 16 + tg;
                int col = n0 + wn + jn * 8 + tc * 2;
                float2 v0 = make_float2(acc[im][jn][0], acc[im][jn][1]);
                float2 v1 = make_float2(acc[im][jn][2], acc[im][jn][3]);
                *(float2*)(C + (size_t)row * N + col) = v0;
                *(float2*)(C + (size_t)(row + 8) * N + col) = v1;
            }
        }
        return;
    }

    // MODE 1: fused rope + scale + fp16 split epilogue (QKV projection)
    const bool isq = (n0 < 4096);
    const bool isk = (n0 >= 4096) && (n0 < 5120);
#pragma unroll
    for (int im = 0; im < 4; im++) {
#pragma unroll
        for (int r2 = 0; r2 < 2; r2++) {
            int t = m0 + wm + im * 16 + tg + r2 * 8;
            int p = pos[t];
#pragma unroll
            for (int jn = 0; jn < 4; jn++) {
                int col = n0 + wn + jn * 8 + tc * 2;
                float a = acc[im][jn][2 * r2 + 0];
                float b = acc[im][jn][2 * r2 + 1];
                if (isq || isk) {
                    int i0 = (col & 127) >> 1;
                    float c = g_cos[p * 64 + i0];
                    float s = g_sin[p * 64 + i0];
                    float na = a * c - b * s;
                    float nb = a * s + b * c;
                    a = na; b = nb;
                }
                if (isq) {
                    a *= QSCALE; b *= QSCALE;
                    __half ha = __float2half_rn(a), hb = __float2half_rn(b);
                    __half la = __float2half_rn(a - __half2float(ha));
                    __half lb = __float2half_rn(b - __half2float(hb));
                    *(__half2*)(qh + (size_t)t * 4096 + col) = __halves2half2(ha, hb);
                    *(__half2*)(ql + (size_t)t * 4096 + col) = __halves2half2(la, lb);
                } else if (isk) {
                    __half ha = __float2half_rn(a), hb = __float2half_rn(b);
                    *(__half2*)(kh + (size_t)t * 1024 + (col - 4096)) = __halves2half2(ha, hb);
                } else {
                    __half ha = __float2half_rn(a), hb = __float2half_rn(b);
                    *(__half2*)(vh + (size_t)t * 1024 + (col - 5120)) = __halves2half2(ha, hb);
                }
            }
        }
    }
}

// =====================  Flash attention (mma.sync fp16, 2-term)  ============
// CTA: 64 q-rows x 64 kv, 4 warps. Tiles: Qh(0) Ql(16K) Kh(32K) Vh(48K), mask @64K.
// Epilogue: hi fp16 -> Oh, lo e5m2 -> Ol8 (out-proj A operands).
#define FL_SMEM (4 * 16384 + 512)

__global__ __launch_bounds__(128) void flash_mma_kernel(
    const __half* __restrict__ Qh, const __half* __restrict__ Ql,
    const __half* __restrict__ Kh, const __half* __restrict__ Vh,
    const float* __restrict__ amask,
    __half* __restrict__ Oh, uint8_t* __restrict__ Ol8)
{
    extern __shared__ __align__(1024) char fsm[];
    const uint32_t sb = smem_u32(fsm);
    float* sMask = (float*)(fsm + 65536);

    const int tid  = threadIdx.x;
    const int warp = tid >> 5;
    const int lane = tid & 31;
    const int tg   = lane >> 2;
    const int tc   = lane & 3;
    const int qt   = (S_ / 64 - 1) - blockIdx.x;   // long tiles first
    const int h    = blockIdx.y;
    const int b    = blockIdx.z;
    const int kvh  = h >> 2;

    // ---- load Q tiles (hi, lo) ----
    {
        const __half* qs[2] = {Qh, Ql};
#pragma unroll
        for (int t = 0; t < 16; t++) {
            int f = t * 128 + tid;
            int tile = t >> 3;
            int ft = f & 1023;
            int r = ft >> 4, c = ft & 15;
            uint32_t dst = sb + (uint32_t)tile * 16384u + (uint32_t)r * 256u +
                           (uint32_t)((c ^ (r & 7)) * 16);
            cp_async16(dst, qs[tile] + (size_t)(b * S_ + qt * 64 + r) * D_ + h * HD + c * 8);
        }
        cp_commit();
    }

    float acc_o[16][4];
#pragma unroll
    for (int i = 0; i < 16; i++)
#pragma unroll
        for (int e = 0; e < 4; e++) acc_o[i][e] = 0.f;
    float m0 = -INFINITY, m1 = -INFINITY, l0 = 0.f, l1 = 0.f;

    const int a_r16  = ((lane >> 3) & 1) * 8 + (lane & 7);
    const int a_cs   = lane >> 4;
    const int b_nsel = lane >> 4;
    const int b_row8 = lane & 7;
    const int b_cs   = (lane >> 3) & 1;
    const int v_half = (lane >> 3) & 1;
    const int v_sel  = lane >> 4;
    const int v_row7 = lane & 7;

    for (int kt = 0; kt <= qt; kt++) {
        if (kt) __syncthreads();
        {
#pragma unroll
            for (int t = 0; t < 8; t++) {
                int f = t * 128 + tid;
                int r = f >> 4, c = f & 15;
                uint32_t dst = sb + 32768u + (uint32_t)r * 256u +
                               (uint32_t)((c ^ (r & 7)) * 16);
                cp_async16(dst, Kh + (size_t)(b * S_ + kt * 64 + r) * KVDIM + kvh * HD + c * 8);
            }
            cp_commit();
#pragma unroll
            for (int t = 0; t < 8; t++) {
                int f = t * 128 + tid;
                int r = f >> 4, c = f & 15;
                uint32_t dst = sb + 49152u + (uint32_t)r * 256u +
                               (uint32_t)((c ^ (r & 7)) * 16);
                cp_async16(dst, Vh + (size_t)(b * S_ + kt * 64 + r) * KVDIM + kvh * HD + c * 8);
            }
            cp_commit();
        }
        if (tid < 64) sMask[tid] = amask[b * S_ + kt * 64 + tid];
        cp_wait<1>();
        __syncthreads();

        // ---- S = Q K^T (qh*kh + ql*kh) ----
        float accs[8][4];
#pragma unroll
        for (int nj = 0; nj < 8; nj++)
#pragma unroll
            for (int e = 0; e < 4; e++) accs[nj][e] = 0.f;

#pragma unroll
        for (int kc = 0; kc < 8; kc++) {
            uint32_t qh4[4], ql4[4];
            {
                int r = warp * 16 + a_r16;
                int cc = kc * 2 + a_cs;
                uint32_t off = (uint32_t)r * 256u + (uint32_t)((cc ^ (r & 7)) * 16);
                ldmatrix_x4(qh4, sb + off);
                ldmatrix_x4(ql4, sb + 16384u + off);
            }
#pragma unroll
            for (int njp = 0; njp < 4; njp++) {
                uint32_t kh4[4];
                int r = (njp * 2 + b_nsel) * 8 + b_row8;
                int cc = kc * 2 + b_cs;
                uint32_t off = (uint32_t)r * 256u + (uint32_t)((cc ^ (r & 7)) * 16);
                ldmatrix_x4(kh4, sb + 32768u + off);
                mma_16816(accs[2 * njp],     qh4, kh4);
                mma_16816(accs[2 * njp],     ql4, kh4);
                mma_16816(accs[2 * njp + 1], qh4, kh4 + 2);
                mma_16816(accs[2 * njp + 1], ql4, kh4 + 2);
            }
        }

        // ---- mask + online softmax ----
        const bool diag = (kt == qt);
        float mx0 = -INFINITY, mx1 = -INFINITY;
#pragma unroll
        for (int nj = 0; nj < 8; nj++) {
#pragma unroll
            for (int e = 0; e < 4; e++) {
                int kvl = nj * 8 + 2 * tc + (e & 1);
                bool valid = sMask[kvl] > 0.f;
                if (diag) {
                    int qloc = warp * 16 + tg + ((e >> 1) ? 8 : 0);
                    valid = valid && (kvl <= qloc);
                }
                float s = valid ? accs[nj][e] : -1e30f;
                accs[nj][e] = s;
                if (e < 2) mx0 = fmaxf(mx0, s); else mx1 = fmaxf(mx1, s);
            }
        }
        mx0 = fmaxf(mx0, __shfl_xor_sync(0xffffffffu, mx0, 1));
        mx0 = fmaxf(mx0, __shfl_xor_sync(0xffffffffu, mx0, 2));
        mx1 = fmaxf(mx1, __shfl_xor_sync(0xffffffffu, mx1, 1));
        mx1 = fmaxf(mx1, __shfl_xor_sync(0xffffffffu, mx1, 2));

        float mn0 = fmaxf(m0, mx0), mn1 = fmaxf(m1, mx1);
        float cr0 = __expf(m0 - mn0), cr1 = __expf(m1 - mn1);
        m0 = mn0; m1 = mn1;

        float s0 = 0.f, s1 = 0.f;
#pragma unroll
        for (int nj = 0; nj < 8; nj++) {
#pragma unroll
            for (int e = 0; e < 4; e++) {
                float p = __expf(accs[nj][e] - ((e < 2) ? m0 : m1));
                accs[nj][e] = p;
                if (e < 2) s0 += p; else s1 += p;
            }
        }
        s0 += __shfl_xor_sync(0xffffffffu, s0, 1);
        s0 += __shfl_xor_sync(0xffffffffu, s0, 2);
        s1 += __shfl_xor_sync(0xffffffffu, s1, 1);
        s1 += __shfl_xor_sync(0xffffffffu, s1, 2);
        l0 = l0 * cr0 + s0;
        l1 = l1 * cr1 + s1;

#pragma unroll
        for (int nd = 0; nd < 16; nd++) {
            acc_o[nd][0] *= cr0; acc_o[nd][1] *= cr0;
            acc_o[nd][2] *= cr1; acc_o[nd][3] *= cr1;
        }

        cp_wait<0>();
        __syncthreads();

        // ---- O += P V (ph*vh + pl*vh) ----
#pragma unroll
        for (int kc2 = 0; kc2 < 4; kc2++) {
            float* p0 = accs[2 * kc2];
            float* p1 = accs[2 * kc2 + 1];
            uint32_t ah[4], al[4];
            ah[0] = pk_f16x2(p0[0], p0[1]);
            ah[1] = pk_f16x2(p0[2], p0[3]);
            ah[2] = pk_f16x2(p1[0], p1[1]);
            ah[3] = pk_f16x2(p1[2], p1[3]);
            {
                float2 f;
                f = unpk_f16x2(ah[0]); al[0] = pk_f16x2(p0[0] - f.x, p0[1] - f.y);
                f = unpk_f16x2(ah[1]); al[1] = pk_f16x2(p0[2] - f.x, p0[3] - f.y);
                f = unpk_f16x2(ah[2]); al[2] = pk_f16x2(p1[0] - f.x, p1[1] - f.y);
                f = unpk_f16x2(ah[3]); al[3] = pk_f16x2(p1[2] - f.x, p1[3] - f.y);
            }
            int vr = kc2 * 16 + v_half * 8 + v_row7;
#pragma unroll
            for (int ndp = 0; ndp < 8; ndp++) {
                int chunk = ndp * 2 + v_sel;
                uint32_t off = (uint32_t)vr * 256u + (uint32_t)((chunk ^ (vr & 7)) * 16);
                uint32_t bh4[4];
                ldmatrix_x4_trans(bh4, sb + 49152u + off);
                mma_16816(acc_o[2 * ndp],     ah, bh4);
                mma_16816(acc_o[2 * ndp],     al, bh4);
                mma_16816(acc_o[2 * ndp + 1], ah, bh4 + 2);
                mma_16816(acc_o[2 * ndp + 1], al, bh4 + 2);
            }
        }
    }

    // ---- normalize + hi fp16 / lo e5m2 write into out-proj A operands ----
    float inv0 = 1.f / l0, inv1 = 1.f / l1;
    int row0 = b * S_ + qt * 64 + warp * 16 + tg;
#pragma unroll
    for (int nd = 0; nd < 16; nd++) {
        int col = h * HD + nd * 8 + 2 * tc;
        float x0 = acc_o[nd][0] * inv0, x1 = acc_o[nd][1] * inv0;
        float x2 = acc_o[nd][2] * inv1, x3 = acc_o[nd][3] * inv1;
        __half h0 = __float2half_rn(x0), h1 = __float2half_rn(x1);
        __half h2 = __float2half_rn(x2), h3 = __float2half_rn(x3);
        *(__half2*)(Oh + (size_t)row0 * KW + col)       = __halves2half2(h0, h1);
        *(__half2*)(Oh + (size_t)(row0 + 8) * KW + col) = __halves2half2(h2, h3);
        uint16_t e01 = pk_e5m2x2(x0 - __half2float(h0), x1 - __half2float(h1));
        uint16_t e23 = pk_e5m2x2(x2 - __half2float(h2), x3 - __half2float(h3));
        *(uint16_t*)(Ol8 + (size_t)row0 * KW + col)       = e01;
        *(uint16_t*)(Ol8 + (size_t)(row0 + 8) * KW + col) = e23;
    }
}

// =====================  launch  =============================================
extern "C" void kernel_launch(void* const* d_in, const int* in_sizes, int n_in,
                              void* d_out, int out_size)
{
    const float* x     = (const float*)d_in[0];
    const float* amask = (const float*)d_in[1];
    const int*   pos   = (const int*)  d_in[2];
    const float* wq    = (const float*)d_in[3];
    const float* wk    = (const float*)d_in[4];
    const float* wv    = (const float*)d_in[5];
    const float* wo    = (const float*)d_in[6];
    float* out = (float*)d_out;

    __half *xh, *qh, *ql, *kh, *vh, *oh, *wh;
    uint8_t *xl8, *ol8, *w8;
    cudaGetSymbolAddress((void**)&xh,  g_Xh);
    cudaGetSymbolAddress((void**)&xl8, g_Xl8);
    cudaGetSymbolAddress((void**)&qh,  g_Qh);
    cudaGetSymbolAddress((void**)&ql,  g_Ql);
    cudaGetSymbolAddress((void**)&kh,  g_Kh);
    cudaGetSymbolAddress((void**)&vh,  g_Vh);
    cudaGetSymbolAddress((void**)&oh,  g_Oh);
    cudaGetSymbolAddress((void**)&ol8, g_Ol8);
    cudaGetSymbolAddress((void**)&wh,  g_Wh);
    cudaGetSymbolAddress((void**)&w8,  g_W8);

    __half*  wqkv_h = wh;                               // rows [0,6144)
    __half*  wo_h   = wh + (size_t)QKVN * KW;           // rows [0,4096)
    uint8_t* wqkv_8 = w8;
    uint8_t* wo_8   = w8 + (size_t)QKVN * KW;

    cudaFuncSetAttribute(gemm_f16_kernel<1>, cudaFuncAttributeMaxDynamicSharedMemorySize, GEMM_SMEM);
    cudaFuncSetAttribute(gemm_f16_kernel<0>, cudaFuncAttributeMaxDynamicSharedMemorySize, GEMM_SMEM);
    cudaFuncSetAttribute(flash_mma_kernel, cudaFuncAttributeMaxDynamicSharedMemorySize, FL_SMEM);

    // RoPE tables (2048 positions)
    rope_table_kernel<<<(2048 * 64) / 256, 256>>>();

    // Conversions: x -> fp16 hi + e5m2 lo; weights -> fp16 + e4m3 transposed
    convert_a_kernel<<<(MTOK * D_ / 4) / 256, 256>>>(x, xh, xl8);
    convert_w_kernel<<<dim3(D_ / 32,    D_ / 32), dim3(32, 8)>>>(wq, wqkv_h, wqkv_8, D_);
    convert_w_kernel<<<dim3(KVDIM / 32, D_ / 32), dim3(32, 8)>>>(wk, wqkv_h + (size_t)4096 * KW, wqkv_8 + (size_t)4096 * KW, KVDIM);
    convert_w_kernel<<<dim3(KVDIM / 32, D_ / 32), dim3(32, 8)>>>(wv, wqkv_h + (size_t)5120 * KW, wqkv_8 + (size_t)5120 * KW, KVDIM);
    convert_w_kernel<<<dim3(D_ / 32,    D_ / 32), dim3(32, 8)>>>(wo, wo_h, wo_8, D_);

    // Fused QKV projection + rope + scale + split (one GEMM, N=6144)
    gemm_f16_kernel<1><<<dim3(MTOK / 128, QKVN / 128), 256, GEMM_SMEM>>>(
        xh, xl8, wqkv_h, wqkv_8, nullptr, QKVN, qh, ql, kh, vh, pos);

    // Attention (tensor-core flash) -> writes Oh fp16 + Ol8 e5m2
    flash_mma_kernel<<<dim3(S_ / 64, NH, B_), 128, FL_SMEM>>>(qh, ql, kh, vh, amask, oh, ol8);

    // Output projection (fp16 hi + fp8 lo, fp32 out)
    gemm_f16_kernel<0><<<dim3(MTOK / 128, D_ / 128), 256, GEMM_SMEM>>>(
        oh, ol8, wo_h, wo_8, out, D_, nullptr, nullptr, nullptr, nullptr, nullptr);
}

// round 14
// speedup vs baseline: 1.1709x; 1.1709x over previous
#include <cuda_runtime.h>
#include <cuda_fp16.h>
#include <cstdint>
#include <math.h>

// Problem constants
#define B_    2
#define S_    2048
#define D_    4096
#define NH    32
#define NKV   8
#define HD    128
#define MTOK  (B_*S_)          // 4096 tokens
#define KVDIM (NKV*HD)         // 1024
#define QKVN  (D_ + 2*KVDIM)   // 6144 fused projection width
#define K2    8192             // split A operand: [hi|lo] fp16
#define KW    4096             // W operand: single fp16
#define QSCALE 0.08838834764831845f
#define ROPE_THETA 500000.0
#define PERSIST_CTAS 296       // 2 CTAs/SM x 148 SMs

// -------------------- scratch (device globals; no allocs allowed) -----------
__device__ float g_cos[2048 * 64];
__device__ float g_sin[2048 * 64];
// x split (32M halves) | qh (16M) | ql (16M) | kh (4M) | vh (4M)  = 72M halves
__device__ __half g_Abf[(size_t)MTOK * 18432];
// attention output, split fp16 [t][K2] (out-proj A operand)
__device__ __half g_Obf[(size_t)MTOK * K2];
// weights single fp16: [qkv rows 0..6144) | wo rows 6144..10240), row stride KW
__device__ __half g_Wbf[(size_t)10240 * KW];

// =====================  PTX helpers (baseline ISA only)  ====================
__device__ __forceinline__ uint32_t smem_u32(const void* p) {
    uint32_t a;
    asm("{ .reg .u64 t; cvta.to.shared.u64 t, %1; cvt.u32.u64 %0, t; }" : "=r"(a) : "l"(p));
    return a;
}
__device__ __forceinline__ void cp_async16(uint32_t s, const void* g) {
    asm volatile("cp.async.cg.shared.global [%0], [%1], 16;" :: "r"(s), "l"(g));
}
__device__ __forceinline__ void cp_commit() {
    asm volatile("cp.async.commit_group;" ::: "memory");
}
template<int N_> __device__ __forceinline__ void cp_wait() {
    asm volatile("cp.async.wait_group %0;" :: "n"(N_) : "memory");
}
__device__ __forceinline__ void ldmatrix_x4(uint32_t* r, uint32_t addr) {
    asm volatile("ldmatrix.sync.aligned.m8n8.x4.shared.b16 {%0,%1,%2,%3}, [%4];"
                 : "=r"(r[0]), "=r"(r[1]), "=r"(r[2]), "=r"(r[3]) : "r"(addr));
}
__device__ __forceinline__ void ldmatrix_x4_trans(uint32_t* r, uint32_t addr) {
    asm volatile("ldmatrix.sync.aligned.m8n8.x4.trans.shared.b16 {%0,%1,%2,%3}, [%4];"
                 : "=r"(r[0]), "=r"(r[1]), "=r"(r[2]), "=r"(r[3]) : "r"(addr));
}
__device__ __forceinline__ void mma_16816(float* d, const uint32_t* a, const uint32_t* b) {
    asm volatile(
        "mma.sync.aligned.m16n8k16.row.col.f32.f16.f16.f32 "
        "{%0,%1,%2,%3}, {%4,%5,%6,%7}, {%8,%9}, {%0,%1,%2,%3};"
        : "+f"(d[0]), "+f"(d[1]), "+f"(d[2]), "+f"(d[3])
        : "r"(a[0]), "r"(a[1]), "r"(a[2]), "r"(a[3]), "r"(b[0]), "r"(b[1]));
}
__device__ __forceinline__ uint32_t pk_f16x2(float lo, float hi) {
    uint32_t d;
    asm("cvt.rn.f16x2.f32 %0, %1, %2;" : "=r"(d) : "f"(hi), "f"(lo));
    return d;
}
__device__ __forceinline__ float2 unpk_f16x2(uint32_t u) {
    __half2 h = *(__half2*)&u;
    return __half22float2(h);
}

// =====================  conversion kernels  =================================
// X[4096][4096] fp32 -> Y[4096][K2] fp16: [0,4096)=hi, [4096,8192)=lo (exact split)
__global__ __launch_bounds__(256) void convert_a_kernel(const float* __restrict__ X,
                                                        __half* __restrict__ Y) {
    int i = blockIdx.x * blockDim.x + threadIdx.x;
    int row = i >> 10;
    int col = (i & 1023) << 2;
    float4 v = ((const float4*)X)[i];
    __half hx = __float2half_rn(v.x);
    __half hy = __float2half_rn(v.y);
    __half hz = __float2half_rn(v.z);
    __half hw = __float2half_rn(v.w);
    __half lx = __float2half_rn(v.x - __half2float(hx));
    __half ly = __float2half_rn(v.y - __half2float(hy));
    __half lz = __float2half_rn(v.z - __half2float(hz));
    __half lw = __float2half_rn(v.w - __half2float(hw));
    size_t base = (size_t)row * K2 + col;
    ((__half2*)(Y + base))[0] = __halves2half2(hx, hy);
    ((__half2*)(Y + base))[1] = __halves2half2(hz, hw);
    ((__half2*)(Y + base + 4096))[0] = __halves2half2(lx, ly);
    ((__half2*)(Y + base + 4096))[1] = __halves2half2(lz, lw);
}

// W[K=4096][N] fp32 -> Y[N][KW] fp16 single, transposed
__global__ __launch_bounds__(256) void convert_w_kernel(const float* __restrict__ W,
                                                        __half* __restrict__ Y, int N) {
    __shared__ float t[32][33];
    int n0 = blockIdx.x * 32;
    int k0 = blockIdx.y * 32;
    int tx = threadIdx.x;
    int ty = threadIdx.y;
#pragma unroll
    for (int i = 0; i < 4; i++)
        t[ty + 8 * i][tx] = W[(size_t)(k0 + ty + 8 * i) * N + n0 + tx];
    __syncthreads();
#pragma unroll
    for (int i = 0; i < 4; i++) {
        int r = ty + 8 * i;
        Y[(size_t)(n0 + r) * KW + k0 + tx] = __float2half_rn(t[tx][r]);
    }
}

// =====================  RoPE table  =========================================
__global__ void rope_table_kernel() {
    int idx = blockIdx.x * blockDim.x + threadIdx.x;
    if (idx >= 2048 * 64) return;
    int p = idx >> 6;
    int i = idx & 63;
    double inv_d = exp(-((double)(2 * i) / (double)HD) * log(ROPE_THETA));
    float invf = (float)inv_d;
    float angf = (float)p * invf;
    g_cos[idx] = (float)cos((double)angf);
    g_sin[idx] = (float)sin((double)angf);
}

// =====================  mma.sync fp16 GEMM (persistent)  ====================
// CTA 128x128, 256 threads (8 warps, 2x4), warp tile 64x32, BK=64, 2 stages.
// Stage = A-hi 16KB | A-lo 16KB | B 16KB (48KB). Both split terms per K-chunk.
// Persistent: grid = PERSIST_CTAS, each CTA loops over tiles (m-fast order).
// MODE 0: C fp32 write. MODE 1: fused rope+scale+split epilogue to q/k/v bufs.
#define BKK 64
#define NST 2
#define STAGE_BYTES 49152
#define GEMM_SMEM (NST * STAGE_BYTES)

__device__ __forceinline__ void gemm_load_stage(
    const __half* __restrict__ A, const __half* __restrict__ Bt,
    int m0, int n0, int it, uint32_t st, int tid)
{
    int kk = it * BKK;
#pragma unroll
    for (int u = 0; u < 4; u++) {             // A-hi
        int f = u * 256 + tid;
        int r = f >> 3;
        int c = f & 7;
        uint32_t sw = (uint32_t)(c ^ (r & 7));
        cp_async16(st + (uint32_t)r * 128u + sw * 16u,
                   A + (size_t)(m0 + r) * K2 + kk + c * 8);
    }
#pragma unroll
    for (int u = 0; u < 4; u++) {             // A-lo
        int f = u * 256 + tid;
        int r = f >> 3;
        int c = f & 7;
        uint32_t sw = (uint32_t)(c ^ (r & 7));
        cp_async16(st + 16384u + (uint32_t)r * 128u + sw * 16u,
                   A + (size_t)(m0 + r) * K2 + 4096 + kk + c * 8);
    }
#pragma unroll
    for (int u = 0; u < 4; u++) {             // B
        int f = u * 256 + tid;
        int r = f >> 3;
        int c = f & 7;
        uint32_t sw = (uint32_t)(c ^ (r & 7));
        cp_async16(st + 32768u + (uint32_t)r * 128u + sw * 16u,
                   Bt + (size_t)(n0 + r) * KW + kk + c * 8);
    }
    cp_commit();
}

template<int MODE>
__global__ __launch_bounds__(256, 2) void gemm_f16_kernel(
    const __half* __restrict__ A, const __half* __restrict__ Bt,
    float* __restrict__ C, int N, int ntiles,
    __half* __restrict__ qh, __half* __restrict__ ql,
    __half* __restrict__ kh, __half* __restrict__ vh,
    const int* __restrict__ pos)
{
    extern __shared__ __align__(1024) char gsm[];
    const uint32_t sbase = smem_u32(gsm);
    const int tid  = threadIdx.x;
    const int wid  = tid >> 5;
    const int lane = tid & 31;
    const int wm = (wid >> 2) * 64;
    const int wn = (wid & 3) * 32;

    const int a_row_in16 = ((lane >> 3) & 1) * 8 + (lane & 7);
    const int a_cadd     = lane >> 4;
    const int b_sel      = lane >> 4;
    const int b_row8     = lane & 7;
    const int b_cs       = (lane >> 3) & 1;
    const int tg = lane >> 2;
    const int tc = lane & 3;

    const int tiles_m = MTOK / 128;   // 32, m fast-moving

    for (int tile = blockIdx.x; tile < ntiles; tile += PERSIST_CTAS) {
        const int m0 = (tile % tiles_m) * 128;
        const int n0 = (tile / tiles_m) * 128;

        float acc[4][4][4];
#pragma unroll
        for (int i = 0; i < 4; i++)
#pragma unroll
            for (int j = 0; j < 4; j++)
#pragma unroll
                for (int e = 0; e < 4; e++) acc[i][j][e] = 0.f;

        const int iters = 64;
        gemm_load_stage(A, Bt, m0, n0, 0, sbase + 0u * STAGE_BYTES, tid);
        gemm_load_stage(A, Bt, m0, n0, 1, sbase + 1u * STAGE_BYTES, tid);

        for (int it = 0; it < iters; it++) {
            cp_wait<1>();
            __syncthreads();

            uint32_t st = sbase + (uint32_t)(it & 1) * STAGE_BYTES;
            uint32_t sAh = st;
            uint32_t sAl = st + 16384u;
            uint32_t sB  = st + 32768u;

#pragma unroll
            for (int ks = 0; ks < 4; ks++) {
                int c0 = ks * 2;
                uint32_t bfr[2][4];
#pragma unroll
                for (int njp = 0; njp < 2; njp++) {
                    int r  = wn + (njp * 2 + b_sel) * 8 + b_row8;
                    int cc = c0 + b_cs;
                    uint32_t addr = sB + (uint32_t)r * 128u + (uint32_t)((cc ^ (r & 7)) * 16);
                    ldmatrix_x4(bfr[njp], addr);
                }
#pragma unroll
                for (int im = 0; im < 4; im++) {
                    int r  = wm + im * 16 + a_row_in16;
                    int cc = c0 + a_cadd;
                    uint32_t aoff = (uint32_t)r * 128u + (uint32_t)((cc ^ (r & 7)) * 16);
                    uint32_t afh[4], afl[4];
                    ldmatrix_x4(afh, sAh + aoff);
                    ldmatrix_x4(afl, sAl + aoff);
#pragma unroll
                    for (int njp = 0; njp < 2; njp++) {
                        mma_16816(acc[im][2 * njp],     afh, bfr[njp]);
                        mma_16816(acc[im][2 * njp],     afl, bfr[njp]);
                        mma_16816(acc[im][2 * njp + 1], afh, bfr[njp] + 2);
                        mma_16816(acc[im][2 * njp + 1], afl, bfr[njp] + 2);
                    }
                }
            }

            __syncthreads();
            if (it + 2 < iters)
                gemm_load_stage(A, Bt, m0, n0, it + 2, st, tid);
        }

        if (MODE == 0) {
#pragma unroll
            for (int im = 0; im < 4; im++) {
#pragma unroll
                for (int jn = 0; jn < 4; jn++) {
                    int row = m0 + wm + im * 16 + tg;
                    int col = n0 + wn + jn * 8 + tc * 2;
                    float2 v0 = make_float2(acc[im][jn][0], acc[im][jn][1]);
                    float2 v1 = make_float2(acc[im][jn][2], acc[im][jn][3]);
                    *(float2*)(C + (size_t)row * N + col) = v0;
                    *(float2*)(C + (size_t)(row + 8) * N + col) = v1;
                }
            }
        } else {
            // fused rope + scale + fp16 split epilogue (QKV projection)
            const bool isq = (n0 < 4096);
            const bool isk = (n0 >= 4096) && (n0 < 5120);
#pragma unroll
            for (int im = 0; im < 4; im++) {
#pragma unroll
                for (int r2 = 0; r2 < 2; r2++) {
                    int t = m0 + wm + im * 16 + tg + r2 * 8;
                    int p = pos[t];
#pragma unroll
                    for (int jn = 0; jn < 4; jn++) {
                        int col = n0 + wn + jn * 8 + tc * 2;
                        float a = acc[im][jn][2 * r2 + 0];
                        float b = acc[im][jn][2 * r2 + 1];
                        if (isq || isk) {
                            int i0 = (col & 127) >> 1;
                            float c = g_cos[p * 64 + i0];
                            float s = g_sin[p * 64 + i0];
                            float na = a * c - b * s;
                            float nb = a * s + b * c;
                            a = na; b = nb;
                        }
                        if (isq) {
                            a *= QSCALE; b *= QSCALE;
                            __half ha = __float2half_rn(a), hb = __float2half_rn(b);
                            __half la = __float2half_rn(a - __half2float(ha));
                            __half lb = __float2half_rn(b - __half2float(hb));
                            *(__half2*)(qh + (size_t)t * 4096 + col) = __halves2half2(ha, hb);
                            *(__half2*)(ql + (size_t)t * 4096 + col) = __halves2half2(la, lb);
                        } else if (isk) {
                            __half ha = __float2half_rn(a), hb = __float2half_rn(b);
                            *(__half2*)(kh + (size_t)t * 1024 + (col - 4096)) = __halves2half2(ha, hb);
                        } else {
                            __half ha = __float2half_rn(a), hb = __float2half_rn(b);
                            *(__half2*)(vh + (size_t)t * 1024 + (col - 5120)) = __halves2half2(ha, hb);
                        }
                    }
                }
            }
        }
    }
}

// =====================  Flash attention (mma.sync fp16, 2-term)  ============
// CTA: 64 q-rows x 64 kv, 4 warps. Tiles: Qh(0) Ql(16K) Kh(32K) Vh(48K), mask @64K.
// Epilogue writes fp16 hi|lo split directly into the out-proj A operand.
#define FL_SMEM (4 * 16384 + 512)

__global__ __launch_bounds__(128) void flash_mma_kernel(
    const __half* __restrict__ Qh, const __half* __restrict__ Ql,
    const __half* __restrict__ Kh, const __half* __restrict__ Vh,
    const float* __restrict__ amask, __half* __restrict__ Obf)
{
    extern __shared__ __align__(1024) char fsm[];
    const uint32_t sb = smem_u32(fsm);
    float* sMask = (float*)(fsm + 65536);

    const int tid  = threadIdx.x;
    const int warp = tid >> 5;
    const int lane = tid & 31;
    const int tg   = lane >> 2;
    const int tc   = lane & 3;
    const int qt   = (S_ / 64 - 1) - blockIdx.x;   // long tiles first
    const int h    = blockIdx.y;
    const int b    = blockIdx.z;
    const int kvh  = h >> 2;

    // ---- load Q tiles (hi, lo) ----
    {
        const __half* qs[2] = {Qh, Ql};
#pragma unroll
        for (int t = 0; t < 16; t++) {
            int f = t * 128 + tid;
            int tile = t >> 3;
            int ft = f & 1023;
            int r = ft >> 4, c = ft & 15;
            uint32_t dst = sb + (uint32_t)tile * 16384u + (uint32_t)r * 256u +
                           (uint32_t)((c ^ (r & 7)) * 16);
            cp_async16(dst, qs[tile] + (size_t)(b * S_ + qt * 64 + r) * D_ + h * HD + c * 8);
        }
        cp_commit();
    }

    float acc_o[16][4];
#pragma unroll
    for (int i = 0; i < 16; i++)
#pragma unroll
        for (int e = 0; e < 4; e++) acc_o[i][e] = 0.f;
    float m0 = -INFINITY, m1 = -INFINITY, l0 = 0.f, l1 = 0.f;

    const int a_r16  = ((lane >> 3) & 1) * 8 + (lane & 7);
    const int a_cs   = lane >> 4;
    const int b_nsel = lane >> 4;
    const int b_row8 = lane & 7;
    const int b_cs   = (lane >> 3) & 1;
    const int v_half = (lane >> 3) & 1;
    const int v_sel  = lane >> 4;
    const int v_row7 = lane & 7;

    for (int kt = 0; kt <= qt; kt++) {
        if (kt) __syncthreads();
        {
#pragma unroll
            for (int t = 0; t < 8; t++) {
                int f = t * 128 + tid;
                int r = f >> 4, c = f & 15;
                uint32_t dst = sb + 32768u + (uint32_t)r * 256u +
                               (uint32_t)((c ^ (r & 7)) * 16);
                cp_async16(dst, Kh + (size_t)(b * S_ + kt * 64 + r) * KVDIM + kvh * HD + c * 8);
            }
            cp_commit();
#pragma unroll
            for (int t = 0; t < 8; t++) {
                int f = t * 128 + tid;
                int r = f >> 4, c = f & 15;
                uint32_t dst = sb + 49152u + (uint32_t)r * 256u +
                               (uint32_t)((c ^ (r & 7)) * 16);
                cp_async16(dst, Vh + (size_t)(b * S_ + kt * 64 + r) * KVDIM + kvh * HD + c * 8);
            }
            cp_commit();
        }
        if (tid < 64) sMask[tid] = amask[b * S_ + kt * 64 + tid];
        cp_wait<1>();
        __syncthreads();

        // ---- S = Q K^T (qh*kh + ql*kh) ----
        float accs[8][4];
#pragma unroll
        for (int nj = 0; nj < 8; nj++)
#pragma unroll
            for (int e = 0; e < 4; e++) accs[nj][e] = 0.f;

#pragma unroll
        for (int kc = 0; kc < 8; kc++) {
            uint32_t qh4[4], ql4[4];
            {
                int r = warp * 16 + a_r16;
                int cc = kc * 2 + a_cs;
                uint32_t off = (uint32_t)r * 256u + (uint32_t)((cc ^ (r & 7)) * 16);
                ldmatrix_x4(qh4, sb + off);
                ldmatrix_x4(ql4, sb + 16384u + off);
            }
#pragma unroll
            for (int njp = 0; njp < 4; njp++) {
                uint32_t kh4[4];
                int r = (njp * 2 + b_nsel) * 8 + b_row8;
                int cc = kc * 2 + b_cs;
                uint32_t off = (uint32_t)r * 256u + (uint32_t)((cc ^ (r & 7)) * 16);
                ldmatrix_x4(kh4, sb + 32768u + off);
                mma_16816(accs[2 * njp],     qh4, kh4);
                mma_16816(accs[2 * njp],     ql4, kh4);
                mma_16816(accs[2 * njp + 1], qh4, kh4 + 2);
                mma_16816(accs[2 * njp + 1], ql4, kh4 + 2);
            }
        }

        // ---- mask + online softmax ----
        const bool diag = (kt == qt);
        float mx0 = -INFINITY, mx1 = -INFINITY;
#pragma unroll
        for (int nj = 0; nj < 8; nj++) {
#pragma unroll
            for (int e = 0; e < 4; e++) {
                int kvl = nj * 8 + 2 * tc + (e & 1);
                bool valid = sMask[kvl] > 0.f;
                if (diag) {
                    int qloc = warp * 16 + tg + ((e >> 1) ? 8 : 0);
                    valid = valid && (kvl <= qloc);
                }
                float s = valid ? accs[nj][e] : -1e30f;
                accs[nj][e] = s;
                if (e < 2) mx0 = fmaxf(mx0, s); else mx1 = fmaxf(mx1, s);
            }
        }
        mx0 = fmaxf(mx0, __shfl_xor_sync(0xffffffffu, mx0, 1));
        mx0 = fmaxf(mx0, __shfl_xor_sync(0xffffffffu, mx0, 2));
        mx1 = fmaxf(mx1, __shfl_xor_sync(0xffffffffu, mx1, 1));
        mx1 = fmaxf(mx1, __shfl_xor_sync(0xffffffffu, mx1, 2));

        float mn0 = fmaxf(m0, mx0), mn1 = fmaxf(m1, mx1);
        float cr0 = __expf(m0 - mn0), cr1 = __expf(m1 - mn1);
        m0 = mn0; m1 = mn1;

        float s0 = 0.f, s1 = 0.f;
#pragma unroll
        for (int nj = 0; nj < 8; nj++) {
#pragma unroll
            for (int e = 0; e < 4; e++) {
                float p = __expf(accs[nj][e] - ((e < 2) ? m0 : m1));
                accs[nj][e] = p;
                if (e < 2) s0 += p; else s1 += p;
            }
        }
        s0 += __shfl_xor_sync(0xffffffffu, s0, 1);
        s0 += __shfl_xor_sync(0xffffffffu, s0, 2);
        s1 += __shfl_xor_sync(0xffffffffu, s1, 1);
        s1 += __shfl_xor_sync(0xffffffffu, s1, 2);
        l0 = l0 * cr0 + s0;
        l1 = l1 * cr1 + s1;

#pragma unroll
        for (int nd = 0; nd < 16; nd++) {
            acc_o[nd][0] *= cr0; acc_o[nd][1] *= cr0;
            acc_o[nd][2] *= cr1; acc_o[nd][3] *= cr1;
        }

        cp_wait<0>();
        __syncthreads();

        // ---- O += P V (ph*vh + pl*vh) ----
#pragma unroll
        for (int kc2 = 0; kc2 < 4; kc2++) {
            float* p0 = accs[2 * kc2];
            float* p1 = accs[2 * kc2 + 1];
            uint32_t ah[4], al[4];
            ah[0] = pk_f16x2(p0[0], p0[1]);
            ah[1] = pk_f16x2(p0[2], p0[3]);
            ah[2] = pk_f16x2(p1[0], p1[1]);
            ah[3] = pk_f16x2(p1[2], p1[3]);
            {
                float2 f;
                f = unpk_f16x2(ah[0]); al[0] = pk_f16x2(p0[0] - f.x, p0[1] - f.y);
                f = unpk_f16x2(ah[1]); al[1] = pk_f16x2(p0[2] - f.x, p0[3] - f.y);
                f = unpk_f16x2(ah[2]); al[2] = pk_f16x2(p1[0] - f.x, p1[1] - f.y);
                f = unpk_f16x2(ah[3]); al[3] = pk_f16x2(p1[2] - f.x, p1[3] - f.y);
            }
            int vr = kc2 * 16 + v_half * 8 + v_row7;
#pragma unroll
            for (int ndp = 0; ndp < 8; ndp++) {
                int chunk = ndp * 2 + v_sel;
                uint32_t off = (uint32_t)vr * 256u + (uint32_t)((chunk ^ (vr & 7)) * 16);
                uint32_t bh4[4];
                ldmatrix_x4_trans(bh4, sb + 49152u + off);
                mma_16816(acc_o[2 * ndp],     ah, bh4);
                mma_16816(acc_o[2 * ndp],     al, bh4);
                mma_16816(acc_o[2 * ndp + 1], ah, bh4 + 2);
                mma_16816(acc_o[2 * ndp + 1], al, bh4 + 2);
            }
        }
    }

    // ---- normalize + split-fp16 write into out-proj A operand ----
    float inv0 = 1.f / l0, inv1 = 1.f / l1;
    int row0 = b * S_ + qt * 64 + warp * 16 + tg;
#pragma unroll
    for (int nd = 0; nd < 16; nd++) {
        int col = h * HD + nd * 8 + 2 * tc;
        float x0 = acc_o[nd][0] * inv0, x1 = acc_o[nd][1] * inv0;
        float x2 = acc_o[nd][2] * inv1, x3 = acc_o[nd][3] * inv1;
        __half h0 = __float2half_rn(x0), h1 = __float2half_rn(x1);
        __half h2 = __float2half_rn(x2), h3 = __float2half_rn(x3);
        __half e0 = __float2half_rn(x0 - __half2float(h0));
        __half e1 = __float2half_rn(x1 - __half2float(h1));
        __half e2 = __float2half_rn(x2 - __half2float(h2));
        __half e3 = __float2half_rn(x3 - __half2float(h3));
        *(__half2*)(Obf + (size_t)row0 * K2 + col)              = __halves2half2(h0, h1);
        *(__half2*)(Obf + (size_t)row0 * K2 + 4096 + col)       = __halves2half2(e0, e1);
        *(__half2*)(Obf + (size_t)(row0 + 8) * K2 + col)        = __halves2half2(h2, h3);
        *(__half2*)(Obf + (size_t)(row0 + 8) * K2 + 4096 + col) = __halves2half2(e2, e3);
    }
}

// =====================  launch  =============================================
extern "C" void kernel_launch(void* const* d_in, const int* in_sizes, int n_in,
                              void* d_out, int out_size)
{
    const float* x     = (const float*)d_in[0];
    const float* amask = (const float*)d_in[1];
    const int*   pos   = (const int*)  d_in[2];
    const float* wq    = (const float*)d_in[3];
    const float* wk    = (const float*)d_in[4];
    const float* wv    = (const float*)d_in[5];
    const float* wo    = (const float*)d_in[6];
    float* out = (float*)d_out;

    __half *abf, *obf, *wbf;
    cudaGetSymbolAddress((void**)&abf, g_Abf);
    cudaGetSymbolAddress((void**)&obf, g_Obf);
    cudaGetSymbolAddress((void**)&wbf, g_Wbf);

    __half* wqkv_h = wbf;                              // rows [0,6144)
    __half* wo_h   = wbf + (size_t)QKVN * KW;          // rows [0,4096)

    // buffer layout inside g_Abf
    const size_t XSZ = (size_t)MTOK * K2;     // 32M halves: x split
    const size_t QSZ = (size_t)MTOK * D_;     // 16M
    const size_t KSZ = (size_t)MTOK * KVDIM;  // 4M
    __half* xs = abf;
    __half* qh = abf + XSZ;
    __half* ql = qh + QSZ;
    __half* kh = ql + QSZ;
    __half* vh = kh + KSZ;

    cudaFuncSetAttribute(gemm_f16_kernel<1>, cudaFuncAttributeMaxDynamicSharedMemorySize, GEMM_SMEM);
    cudaFuncSetAttribute(gemm_f16_kernel<0>, cudaFuncAttributeMaxDynamicSharedMemorySize, GEMM_SMEM);
    cudaFuncSetAttribute(flash_mma_kernel, cudaFuncAttributeMaxDynamicSharedMemorySize, FL_SMEM);

    // RoPE tables (2048 positions)
    rope_table_kernel<<<(2048 * 64) / 256, 256>>>();

    // Conversions: x split fp16, weights single fp16 transposed
    convert_a_kernel<<<(MTOK * D_ / 4) / 256, 256>>>(x, xs);
    convert_w_kernel<<<dim3(D_ / 32,    D_ / 32), dim3(32, 8)>>>(wq, wqkv_h, D_);
    convert_w_kernel<<<dim3(KVDIM / 32, D_ / 32), dim3(32, 8)>>>(wk, wqkv_h + (size_t)4096 * KW, KVDIM);
    convert_w_kernel<<<dim3(KVDIM / 32, D_ / 32), dim3(32, 8)>>>(wv, wqkv_h + (size_t)5120 * KW, KVDIM);
    convert_w_kernel<<<dim3(D_ / 32,    D_ / 32), dim3(32, 8)>>>(wo, wo_h, D_);

    // Fused QKV projection + rope + scale + fp16 split (persistent GEMM, N=6144)
    gemm_f16_kernel<1><<<PERSIST_CTAS, 256, GEMM_SMEM>>>(
        xs, wqkv_h, nullptr, QKVN, (MTOK / 128) * (QKVN / 128), qh, ql, kh, vh, pos);

    // Attention (tensor-core flash) -> writes split fp16 out-proj operand
    flash_mma_kernel<<<dim3(S_ / 64, NH, B_), 128, FL_SMEM>>>(qh, ql, kh, vh, amask, obf);

    // Output projection (2-term split A, fp32 out, persistent GEMM)
    gemm_f16_kernel<0><<<PERSIST_CTAS, 256, GEMM_SMEM>>>(
        obf, wo_h, out, D_, (MTOK / 128) * (D_ / 128), nullptr, nullptr, nullptr, nullptr, nullptr);
}

// round 15
// speedup vs baseline: 1.1991x; 1.0240x over previous
#include <cuda_runtime.h>
#include <cuda_fp16.h>
#include <cstdint>
#include <math.h>

// Problem constants
#define B_    2
#define S_    2048
#define D_    4096
#define NH    32
#define NKV   8
#define HD    128
#define MTOK  (B_*S_)          // 4096 tokens
#define KVDIM (NKV*HD)         // 1024
#define QKVN  (D_ + 2*KVDIM)   // 6144 fused projection width
#define K2    8192             // split A operand: [hi|lo] fp16
#define KW    4096             // W operand: single fp16
#define QSCALE 0.08838834764831845f
#define ROPE_THETA 500000.0

// -------------------- scratch (device globals; no allocs allowed) -----------
__device__ float g_cos[2048 * 64];
__device__ float g_sin[2048 * 64];
// x split (32M halves) | qh (16M) | ql (16M) | kh (4M) | vh (4M)  = 72M halves
__device__ __half g_Abf[(size_t)MTOK * 18432];
// attention output, split fp16 [t][K2] (out-proj A operand)
__device__ __half g_Obf[(size_t)MTOK * K2];
// weights single fp16: [qkv rows 0..6144) | wo rows 6144..10240), row stride KW
__device__ __half g_Wbf[(size_t)10240 * KW];

// =====================  PTX helpers (baseline ISA only)  ====================
__device__ __forceinline__ uint32_t smem_u32(const void* p) {
    uint32_t a;
    asm("{ .reg .u64 t; cvta.to.shared.u64 t, %1; cvt.u32.u64 %0, t; }" : "=r"(a) : "l"(p));
    return a;
}
__device__ __forceinline__ void cp_async16(uint32_t s, const void* g) {
    asm volatile("cp.async.cg.shared.global [%0], [%1], 16;" :: "r"(s), "l"(g));
}
__device__ __forceinline__ void cp_commit() {
    asm volatile("cp.async.commit_group;" ::: "memory");
}
template<int N_> __device__ __forceinline__ void cp_wait() {
    asm volatile("cp.async.wait_group %0;" :: "n"(N_) : "memory");
}
__device__ __forceinline__ void ldmatrix_x4(uint32_t* r, uint32_t addr) {
    asm volatile("ldmatrix.sync.aligned.m8n8.x4.shared.b16 {%0,%1,%2,%3}, [%4];"
                 : "=r"(r[0]), "=r"(r[1]), "=r"(r[2]), "=r"(r[3]) : "r"(addr));
}
__device__ __forceinline__ void ldmatrix_x4_trans(uint32_t* r, uint32_t addr) {
    asm volatile("ldmatrix.sync.aligned.m8n8.x4.trans.shared.b16 {%0,%1,%2,%3}, [%4];"
                 : "=r"(r[0]), "=r"(r[1]), "=r"(r[2]), "=r"(r[3]) : "r"(addr));
}
__device__ __forceinline__ void mma_16816(float* d, const uint32_t* a, const uint32_t* b) {
    asm volatile(
        "mma.sync.aligned.m16n8k16.row.col.f32.f16.f16.f32 "
        "{%0,%1,%2,%3}, {%4,%5,%6,%7}, {%8,%9}, {%0,%1,%2,%3};"
        : "+f"(d[0]), "+f"(d[1]), "+f"(d[2]), "+f"(d[3])
        : "r"(a[0]), "r"(a[1]), "r"(a[2]), "r"(a[3]), "r"(b[0]), "r"(b[1]));
}
__device__ __forceinline__ uint32_t pk_f16x2(float lo, float hi) {
    uint32_t d;
    asm("cvt.rn.f16x2.f32 %0, %1, %2;" : "=r"(d) : "f"(hi), "f"(lo));
    return d;
}
__device__ __forceinline__ float2 unpk_f16x2(uint32_t u) {
    __half2 h = *(__half2*)&u;
    return __half22float2(h);
}

// =====================  conversion kernels  =================================
// X[4096][4096] fp32 -> Y[4096][K2] fp16: [0,4096)=hi, [4096,8192)=lo (exact split)
__global__ __launch_bounds__(256) void convert_a_kernel(const float* __restrict__ X,
                                                        __half* __restrict__ Y) {
    int i = blockIdx.x * blockDim.x + threadIdx.x;
    int row = i >> 10;
    int col = (i & 1023) << 2;
    float4 v = ((const float4*)X)[i];
    __half hx = __float2half_rn(v.x);
    __half hy = __float2half_rn(v.y);
    __half hz = __float2half_rn(v.z);
    __half hw = __float2half_rn(v.w);
    __half lx = __float2half_rn(v.x - __half2float(hx));
    __half ly = __float2half_rn(v.y - __half2float(hy));
    __half lz = __float2half_rn(v.z - __half2float(hz));
    __half lw = __float2half_rn(v.w - __half2float(hw));
    size_t base = (size_t)row * K2 + col;
    ((__half2*)(Y + base))[0] = __halves2half2(hx, hy);
    ((__half2*)(Y + base))[1] = __halves2half2(hz, hw);
    ((__half2*)(Y + base + 4096))[0] = __halves2half2(lx, ly);
    ((__half2*)(Y + base + 4096))[1] = __halves2half2(lz, lw);
}

// W[K=4096][N] fp32 -> Y[N][KW] fp16 single, transposed
__global__ __launch_bounds__(256) void convert_w_kernel(const float* __restrict__ W,
                                                        __half* __restrict__ Y, int N) {
    __shared__ float t[32][33];
    int n0 = blockIdx.x * 32;
    int k0 = blockIdx.y * 32;
    int tx = threadIdx.x;
    int ty = threadIdx.y;
#pragma unroll
    for (int i = 0; i < 4; i++)
        t[ty + 8 * i][tx] = W[(size_t)(k0 + ty + 8 * i) * N + n0 + tx];
    __syncthreads();
#pragma unroll
    for (int i = 0; i < 4; i++) {
        int r = ty + 8 * i;
        Y[(size_t)(n0 + r) * KW + k0 + tx] = __float2half_rn(t[tx][r]);
    }
}

// =====================  RoPE table  =========================================
// Match the reference rounding: angle = fp32(p) * fp32(inv_freq) computed in
// fp32 (like jnp.outer), then accurate trig of that fp32 angle.
__global__ void rope_table_kernel() {
    int idx = blockIdx.x * blockDim.x + threadIdx.x;
    if (idx >= 2048 * 64) return;
    int p = idx >> 6;
    int i = idx & 63;
    double inv_d = exp(-((double)(2 * i) / (double)HD) * log(ROPE_THETA));
    float invf = (float)inv_d;
    float angf = (float)p * invf;          // fp32 product, as in the reference
    g_cos[idx] = (float)cos((double)angf);
    g_sin[idx] = (float)sin((double)angf);
}

// =====================  mma.sync fp16 GEMM  =================================
// CTA 128x128, 256 threads (8 warps, 2x4), warp tile 64x32, BK=64, 2 stages.
// Stage = A-hi 16KB | A-lo 16KB | B 16KB (48KB). Both split terms computed per
// K-chunk, so B is staged ONCE per chunk.
// MODE 0: C fp32 write. MODE 1: fused rope+scale+split epilogue to q/k/v bufs.
#define BKK 64
#define NST 2
#define STAGE_BYTES 49152
#define GEMM_SMEM (NST * STAGE_BYTES)

__device__ __forceinline__ void gemm_load_stage(
    const __half* __restrict__ A, const __half* __restrict__ Bt,
    int m0, int n0, int it, uint32_t st, int tid)
{
    int kk = it * BKK;
#pragma unroll
    for (int u = 0; u < 4; u++) {             // A-hi
        int f = u * 256 + tid;
        int r = f >> 3;
        int c = f & 7;
        uint32_t sw = (uint32_t)(c ^ (r & 7));
        cp_async16(st + (uint32_t)r * 128u + sw * 16u,
                   A + (size_t)(m0 + r) * K2 + kk + c * 8);
    }
#pragma unroll
    for (int u = 0; u < 4; u++) {             // A-lo
        int f = u * 256 + tid;
        int r = f >> 3;
        int c = f & 7;
        uint32_t sw = (uint32_t)(c ^ (r & 7));
        cp_async16(st + 16384u + (uint32_t)r * 128u + sw * 16u,
                   A + (size_t)(m0 + r) * K2 + 4096 + kk + c * 8);
    }
#pragma unroll
    for (int u = 0; u < 4; u++) {             // B
        int f = u * 256 + tid;
        int r = f >> 3;
        int c = f & 7;
        uint32_t sw = (uint32_t)(c ^ (r & 7));
        cp_async16(st + 32768u + (uint32_t)r * 128u + sw * 16u,
                   Bt + (size_t)(n0 + r) * KW + kk + c * 8);
    }
    cp_commit();
}

template<int MODE>
__global__ __launch_bounds__(256, 2) void gemm_f16_kernel(
    const __half* __restrict__ A, const __half* __restrict__ Bt,
    float* __restrict__ C, int N,
    __half* __restrict__ qh, __half* __restrict__ ql,
    __half* __restrict__ kh, __half* __restrict__ vh,
    const int* __restrict__ pos)
{
    extern __shared__ __align__(1024) char gsm[];
    const uint32_t sbase = smem_u32(gsm);
    const int tid  = threadIdx.x;
    const int wid  = tid >> 5;
    const int lane = tid & 31;

    const int m0 = blockIdx.x * 128;
    const int n0 = blockIdx.y * 128;
    const int wm = (wid >> 2) * 64;
    const int wn = (wid & 3) * 32;

    float acc[4][4][4];
#pragma unroll
    for (int i = 0; i < 4; i++)
#pragma unroll
        for (int j = 0; j < 4; j++)
#pragma unroll
            for (int e = 0; e < 4; e++) acc[i][j][e] = 0.f;

    const int iters = 64;   // 64 K-chunks of 64; both terms per chunk
    gemm_load_stage(A, Bt, m0, n0, 0, sbase + 0u * STAGE_BYTES, tid);
    gemm_load_stage(A, Bt, m0, n0, 1, sbase + 1u * STAGE_BYTES, tid);

    const int a_row_in16 = ((lane >> 3) & 1) * 8 + (lane & 7);
    const int a_cadd     = lane >> 4;
    const int b_sel      = lane >> 4;
    const int b_row8     = lane & 7;
    const int b_cs       = (lane >> 3) & 1;

    for (int it = 0; it < iters; it++) {
        cp_wait<1>();
        __syncthreads();

        uint32_t st = sbase + (uint32_t)(it & 1) * STAGE_BYTES;
        uint32_t sAh = st;
        uint32_t sAl = st + 16384u;
        uint32_t sB  = st + 32768u;

#pragma unroll
        for (int ks = 0; ks < 4; ks++) {
            int c0 = ks * 2;
            uint32_t bfr[2][4];
#pragma unroll
            for (int njp = 0; njp < 2; njp++) {
                int r  = wn + (njp * 2 + b_sel) * 8 + b_row8;
                int cc = c0 + b_cs;
                uint32_t addr = sB + (uint32_t)r * 128u + (uint32_t)((cc ^ (r & 7)) * 16);
                ldmatrix_x4(bfr[njp], addr);
            }
#pragma unroll
            for (int im = 0; im < 4; im++) {
                int r  = wm + im * 16 + a_row_in16;
                int cc = c0 + a_cadd;
                uint32_t aoff = (uint32_t)r * 128u + (uint32_t)((cc ^ (r & 7)) * 16);
                uint32_t afh[4], afl[4];
                ldmatrix_x4(afh, sAh + aoff);
                ldmatrix_x4(afl, sAl + aoff);
#pragma unroll
                for (int njp = 0; njp < 2; njp++) {
                    mma_16816(acc[im][2 * njp],     afh, bfr[njp]);
                    mma_16816(acc[im][2 * njp],     afl, bfr[njp]);
                    mma_16816(acc[im][2 * njp + 1], afh, bfr[njp] + 2);
                    mma_16816(acc[im][2 * njp + 1], afl, bfr[njp] + 2);
                }
            }
        }

        __syncthreads();     // all warps done with this buffer before refill
        if (it + 2 < iters)
            gemm_load_stage(A, Bt, m0, n0, it + 2, st, tid);
    }

    const int tg = lane >> 2;
    const int tc = lane & 3;

    if (MODE == 0) {
#pragma unroll
        for (int im = 0; im < 4; im++) {
#pragma unroll
            for (int jn = 0; jn < 4; jn++) {
                int row = m0 + wm + im * 16 + tg;
                int col = n0 + wn + jn * 8 + tc * 2;
                float2 v0 = make_float2(acc[im][jn][0], acc[im][jn][1]);
                float2 v1 = make_float2(acc[im][jn][2], acc[im][jn][3]);
                *(float2*)(C + (size_t)row * N + col) = v0;
                *(float2*)(C + (size_t)(row + 8) * N + col) = v1;
            }
        }
        return;
    }

    // MODE 1: fused rope + scale + fp16 split epilogue (QKV projection)
    const bool isq = (n0 < 4096);
    const bool isk = (n0 >= 4096) && (n0 < 5120);
#pragma unroll
    for (int im = 0; im < 4; im++) {
#pragma unroll
        for (int r2 = 0; r2 < 2; r2++) {
            int t = m0 + wm + im * 16 + tg + r2 * 8;
            int p = pos[t];
#pragma unroll
            for (int jn = 0; jn < 4; jn++) {
                int col = n0 + wn + jn * 8 + tc * 2;
                float a = acc[im][jn][2 * r2 + 0];
                float b = acc[im][jn][2 * r2 + 1];
                if (isq || isk) {
                    int i0 = (col & 127) >> 1;
                    float c = g_cos[p * 64 + i0];
                    float s = g_sin[p * 64 + i0];
                    float na = a * c - b * s;
                    float nb = a * s + b * c;
                    a = na; b = nb;
                }
                if (isq) {
                    a *= QSCALE; b *= QSCALE;
                    __half ha = __float2half_rn(a), hb = __float2half_rn(b);
                    __half la = __float2half_rn(a - __half2float(ha));
                    __half lb = __float2half_rn(b - __half2float(hb));
                    *(__half2*)(qh + (size_t)t * 4096 + col) = __halves2half2(ha, hb);
                    *(__half2*)(ql + (size_t)t * 4096 + col) = __halves2half2(la, lb);
                } else if (isk) {
                    __half ha = __float2half_rn(a), hb = __float2half_rn(b);
                    *(__half2*)(kh + (size_t)t * 1024 + (col - 4096)) = __halves2half2(ha, hb);
                } else {
                    __half ha = __float2half_rn(a), hb = __float2half_rn(b);
                    *(__half2*)(vh + (size_t)t * 1024 + (col - 5120)) = __halves2half2(ha, hb);
                }
            }
        }
    }
}

// =====================  Flash attention (mma.sync fp16, 2-term)  ============
// CTA: 64 q-rows x 64 kv, 4 warps. Tiles: Qh(0) Ql(16K) Kh(32K) Vh(48K), mask @64K.
// Epilogue writes fp16 hi|lo split directly into the out-proj A operand.
#define FL_SMEM (4 * 16384 + 512)

__global__ __launch_bounds__(128) void flash_mma_kernel(
    const __half* __restrict__ Qh, const __half* __restrict__ Ql,
    const __half* __restrict__ Kh, const __half* __restrict__ Vh,
    const float* __restrict__ amask, __half* __restrict__ Obf)
{
    extern __shared__ __align__(1024) char fsm[];
    const uint32_t sb = smem_u32(fsm);
    float* sMask = (float*)(fsm + 65536);

    const int tid  = threadIdx.x;
    const int warp = tid >> 5;
    const int lane = tid & 31;
    const int tg   = lane >> 2;
    const int tc   = lane & 3;
    const int qt   = (S_ / 64 - 1) - blockIdx.x;   // long tiles first
    const int h    = blockIdx.y;
    const int b    = blockIdx.z;
    const int kvh  = h >> 2;

    // ---- load Q tiles (hi, lo) ----
    {
        const __half* qs[2] = {Qh, Ql};
#pragma unroll
        for (int t = 0; t < 16; t++) {
            int f = t * 128 + tid;
            int tile = t >> 3;
            int ft = f & 1023;
            int r = ft >> 4, c = ft & 15;
            uint32_t dst = sb + (uint32_t)tile * 16384u + (uint32_t)r * 256u +
                           (uint32_t)((c ^ (r & 7)) * 16);
            cp_async16(dst, qs[tile] + (size_t)(b * S_ + qt * 64 + r) * D_ + h * HD + c * 8);
        }
        cp_commit();
    }

    float acc_o[16][4];
#pragma unroll
    for (int i = 0; i < 16; i++)
#pragma unroll
        for (int e = 0; e < 4; e++) acc_o[i][e] = 0.f;
    float m0 = -INFINITY, m1 = -INFINITY, l0 = 0.f, l1 = 0.f;

    const int a_r16  = ((lane >> 3) & 1) * 8 + (lane & 7);
    const int a_cs   = lane >> 4;
    const int b_nsel = lane >> 4;
    const int b_row8 = lane & 7;
    const int b_cs   = (lane >> 3) & 1;
    const int v_half = (lane >> 3) & 1;
    const int v_sel  = lane >> 4;
    const int v_row7 = lane & 7;

    for (int kt = 0; kt <= qt; kt++) {
        if (kt) __syncthreads();     // all warps done reading prev K/V
        // ---- load K tile then V tile, separate commit groups ----
        {
#pragma unroll
            for (int t = 0; t < 8; t++) {
                int f = t * 128 + tid;
                int r = f >> 4, c = f & 15;
                uint32_t dst = sb + 32768u + (uint32_t)r * 256u +
                               (uint32_t)((c ^ (r & 7)) * 16);
                cp_async16(dst, Kh + (size_t)(b * S_ + kt * 64 + r) * KVDIM + kvh * HD + c * 8);
            }
            cp_commit();
#pragma unroll
            for (int t = 0; t < 8; t++) {
                int f = t * 128 + tid;
                int r = f >> 4, c = f & 15;
                uint32_t dst = sb + 49152u + (uint32_t)r * 256u +
                               (uint32_t)((c ^ (r & 7)) * 16);
                cp_async16(dst, Vh + (size_t)(b * S_ + kt * 64 + r) * KVDIM + kvh * HD + c * 8);
            }
            cp_commit();
        }
        if (tid < 64) sMask[tid] = amask[b * S_ + kt * 64 + tid];
        cp_wait<1>();                 // K (and Q on first iter) ready; V in flight
        __syncthreads();

        // ---- S = Q K^T (qh*kh + ql*kh) ----
        float accs[8][4];
#pragma unroll
        for (int nj = 0; nj < 8; nj++)
#pragma unroll
            for (int e = 0; e < 4; e++) accs[nj][e] = 0.f;

#pragma unroll
        for (int kc = 0; kc < 8; kc++) {
            uint32_t qh4[4], ql4[4];
            {
                int r = warp * 16 + a_r16;
                int cc = kc * 2 + a_cs;
                uint32_t off = (uint32_t)r * 256u + (uint32_t)((cc ^ (r & 7)) * 16);
                ldmatrix_x4(qh4, sb + off);
                ldmatrix_x4(ql4, sb + 16384u + off);
            }
#pragma unroll
            for (int njp = 0; njp < 4; njp++) {
                uint32_t kh4[4];
                int r = (njp * 2 + b_nsel) * 8 + b_row8;
                int cc = kc * 2 + b_cs;
                uint32_t off = (uint32_t)r * 256u + (uint32_t)((cc ^ (r & 7)) * 16);
                ldmatrix_x4(kh4, sb + 32768u + off);
                mma_16816(accs[2 * njp],     qh4, kh4);
                mma_16816(accs[2 * njp],     ql4, kh4);
                mma_16816(accs[2 * njp + 1], qh4, kh4 + 2);
                mma_16816(accs[2 * njp + 1], ql4, kh4 + 2);
            }
        }

        // ---- mask + online softmax ----
        const bool diag = (kt == qt);
        float mx0 = -INFINITY, mx1 = -INFINITY;
#pragma unroll
        for (int nj = 0; nj < 8; nj++) {
#pragma unroll
            for (int e = 0; e < 4; e++) {
                int kvl = nj * 8 + 2 * tc + (e & 1);
                bool valid = sMask[kvl] > 0.f;
                if (diag) {
                    int qloc = warp * 16 + tg + ((e >> 1) ? 8 : 0);
                    valid = valid && (kvl <= qloc);
                }
                float s = valid ? accs[nj][e] : -1e30f;
                accs[nj][e] = s;
                if (e < 2) mx0 = fmaxf(mx0, s); else mx1 = fmaxf(mx1, s);
            }
        }
        mx0 = fmaxf(mx0, __shfl_xor_sync(0xffffffffu, mx0, 1));
        mx0 = fmaxf(mx0, __shfl_xor_sync(0xffffffffu, mx0, 2));
        mx1 = fmaxf(mx1, __shfl_xor_sync(0xffffffffu, mx1, 1));
        mx1 = fmaxf(mx1, __shfl_xor_sync(0xffffffffu, mx1, 2));

        float mn0 = fmaxf(m0, mx0), mn1 = fmaxf(m1, mx1);
        float cr0 = __expf(m0 - mn0), cr1 = __expf(m1 - mn1);
        m0 = mn0; m1 = mn1;

        float s0 = 0.f, s1 = 0.f;
#pragma unroll
        for (int nj = 0; nj < 8; nj++) {
#pragma unroll
            for (int e = 0; e < 4; e++) {
                float p = __expf(accs[nj][e] - ((e < 2) ? m0 : m1));
                accs[nj][e] = p;
                if (e < 2) s0 += p; else s1 += p;
            }
        }
        s0 += __shfl_xor_sync(0xffffffffu, s0, 1);
        s0 += __shfl_xor_sync(0xffffffffu, s0, 2);
        s1 += __shfl_xor_sync(0xffffffffu, s1, 1);
        s1 += __shfl_xor_sync(0xffffffffu, s1, 2);
        l0 = l0 * cr0 + s0;
        l1 = l1 * cr1 + s1;

#pragma unroll
        for (int nd = 0; nd < 16; nd++) {
            acc_o[nd][0] *= cr0; acc_o[nd][1] *= cr0;
            acc_o[nd][2] *= cr1; acc_o[nd][3] *= cr1;
        }

        cp_wait<0>();                 // V now ready
        __syncthreads();

        // ---- O += P V (ph*vh + pl*vh) ----
#pragma unroll
        for (int kc2 = 0; kc2 < 4; kc2++) {
            float* p0 = accs[2 * kc2];
            float* p1 = accs[2 * kc2 + 1];
            uint32_t ah[4], al[4];
            ah[0] = pk_f16x2(p0[0], p0[1]);
            ah[1] = pk_f16x2(p0[2], p0[3]);
            ah[2] = pk_f16x2(p1[0], p1[1]);
            ah[3] = pk_f16x2(p1[2], p1[3]);
            {
                float2 f;
                f = unpk_f16x2(ah[0]); al[0] = pk_f16x2(p0[0] - f.x, p0[1] - f.y);
                f = unpk_f16x2(ah[1]); al[1] = pk_f16x2(p0[2] - f.x, p0[3] - f.y);
                f = unpk_f16x2(ah[2]); al[2] = pk_f16x2(p1[0] - f.x, p1[1] - f.y);
                f = unpk_f16x2(ah[3]); al[3] = pk_f16x2(p1[2] - f.x, p1[3] - f.y);
            }
            int vr = kc2 * 16 + v_half * 8 + v_row7;
#pragma unroll
            for (int ndp = 0; ndp < 8; ndp++) {
                int chunk = ndp * 2 + v_sel;
                uint32_t off = (uint32_t)vr * 256u + (uint32_t)((chunk ^ (vr & 7)) * 16);
                uint32_t bh4[4];
                ldmatrix_x4_trans(bh4, sb + 49152u + off);
                mma_16816(acc_o[2 * ndp],     ah, bh4);
                mma_16816(acc_o[2 * ndp],     al, bh4);
                mma_16816(acc_o[2 * ndp + 1], ah, bh4 + 2);
                mma_16816(acc_o[2 * ndp + 1], al, bh4 + 2);
            }
        }
    }

    // ---- normalize + split-fp16 write into out-proj A operand ----
    float inv0 = 1.f / l0, inv1 = 1.f / l1;
    int row0 = b * S_ + qt * 64 + warp * 16 + tg;
#pragma unroll
    for (int nd = 0; nd < 16; nd++) {
        int col = h * HD + nd * 8 + 2 * tc;
        float x0 = acc_o[nd][0] * inv0, x1 = acc_o[nd][1] * inv0;
        float x2 = acc_o[nd][2] * inv1, x3 = acc_o[nd][3] * inv1;
        __half h0 = __float2half_rn(x0), h1 = __float2half_rn(x1);
        __half h2 = __float2half_rn(x2), h3 = __float2half_rn(x3);
        __half e0 = __float2half_rn(x0 - __half2float(h0));
        __half e1 = __float2half_rn(x1 - __half2float(h1));
        __half e2 = __float2half_rn(x2 - __half2float(h2));
        __half e3 = __float2half_rn(x3 - __half2float(h3));
        *(__half2*)(Obf + (size_t)row0 * K2 + col)              = __halves2half2(h0, h1);
        *(__half2*)(Obf + (size_t)row0 * K2 + 4096 + col)       = __halves2half2(e0, e1);
        *(__half2*)(Obf + (size_t)(row0 + 8) * K2 + col)        = __halves2half2(h2, h3);
        *(__half2*)(Obf + (size_t)(row0 + 8) * K2 + 4096 + col) = __halves2half2(e2, e3);
    }
}

// =====================  launch  =============================================
extern "C" void kernel_launch(void* const* d_in, const int* in_sizes, int n_in,
                              void* d_out, int out_size)
{
    const float* x     = (const float*)d_in[0];
    const float* amask = (const float*)d_in[1];
    const int*   pos   = (const int*)  d_in[2];
    const float* wq    = (const float*)d_in[3];
    const float* wk    = (const float*)d_in[4];
    const float* wv    = (const float*)d_in[5];
    const float* wo    = (const float*)d_in[6];
    float* out = (float*)d_out;

    __half *abf, *obf, *wbf;
    cudaGetSymbolAddress((void**)&abf, g_Abf);
    cudaGetSymbolAddress((void**)&obf, g_Obf);
    cudaGetSymbolAddress((void**)&wbf, g_Wbf);

    __half* wqkv_h = wbf;                              // rows [0,6144)
    __half* wo_h   = wbf + (size_t)QKVN * KW;          // rows [0,4096)

    // buffer layout inside g_Abf
    const size_t XSZ = (size_t)MTOK * K2;     // 32M halves: x split
    const size_t QSZ = (size_t)MTOK * D_;     // 16M
    const size_t KSZ = (size_t)MTOK * KVDIM;  // 4M
    __half* xs = abf;
    __half* qh = abf + XSZ;
    __half* ql = qh + QSZ;
    __half* kh = ql + QSZ;
    __half* vh = kh + KSZ;

    cudaFuncSetAttribute(gemm_f16_kernel<1>, cudaFuncAttributeMaxDynamicSharedMemorySize, GEMM_SMEM);
    cudaFuncSetAttribute(gemm_f16_kernel<0>, cudaFuncAttributeMaxDynamicSharedMemorySize, GEMM_SMEM);
    cudaFuncSetAttribute(flash_mma_kernel, cudaFuncAttributeMaxDynamicSharedMemorySize, FL_SMEM);

    // RoPE tables (2048 positions)
    rope_table_kernel<<<(2048 * 64) / 256, 256>>>();

    // Conversions: x split fp16, weights single fp16 transposed
    convert_a_kernel<<<(MTOK * D_ / 4) / 256, 256>>>(x, xs);
    convert_w_kernel<<<dim3(D_ / 32,    D_ / 32), dim3(32, 8)>>>(wq, wqkv_h, D_);
    convert_w_kernel<<<dim3(KVDIM / 32, D_ / 32), dim3(32, 8)>>>(wk, wqkv_h + (size_t)4096 * KW, KVDIM);
    convert_w_kernel<<<dim3(KVDIM / 32, D_ / 32), dim3(32, 8)>>>(wv, wqkv_h + (size_t)5120 * KW, KVDIM);
    convert_w_kernel<<<dim3(D_ / 32,    D_ / 32), dim3(32, 8)>>>(wo, wo_h, D_);

    // Fused QKV projection + rope + scale + fp16 split (one GEMM, N=6144)
    gemm_f16_kernel<1><<<dim3(MTOK / 128, QKVN / 128), 256, GEMM_SMEM>>>(
        xs, wqkv_h, nullptr, QKVN, qh, ql, kh, vh, pos);

    // Attention (tensor-core flash) -> writes split fp16 out-proj operand
    flash_mma_kernel<<<dim3(S_ / 64, NH, B_), 128, FL_SMEM>>>(qh, ql, kh, vh, amask, obf);

    // Output projection (2-term split A, fp32 out)
    gemm_f16_kernel<0><<<dim3(MTOK / 128, D_ / 128), 256, GEMM_SMEM>>>(
        obf, wo_h, out, D_, nullptr, nullptr, nullptr, nullptr, nullptr);
}

// round 16
// speedup vs baseline: 1.2023x; 1.0027x over previous
#include <cuda_runtime.h>
#include <cuda_fp16.h>
#include <cstdint>
#include <math.h>

// Problem constants
#define B_    2
#define S_    2048
#define D_    4096
#define NH    32
#define NKV   8
#define HD    128
#define MTOK  (B_*S_)          // 4096 tokens
#define KVDIM (NKV*HD)         // 1024
#define QKVN  (D_ + 2*KVDIM)   // 6144 fused projection width
#define K2    8192             // split A operand: [hi|lo] fp16
#define KW    4096             // W operand: single fp16
#define QSCALE 0.08838834764831845f
#define ROPE_THETA 500000.0

// -------------------- scratch (device globals; no allocs allowed) -----------
__device__ float g_cos[2048 * 64];
__device__ float g_sin[2048 * 64];
// x split (32M halves) | qh (16M) | ql (16M) | kh (4M) | vh (4M)  = 72M halves
__device__ __half g_Abf[(size_t)MTOK * 18432];
// attention output, split fp16 [t][K2] (out-proj A operand)
__device__ __half g_Obf[(size_t)MTOK * K2];
// weights single fp16: [qkv rows 0..6144) | wo rows 6144..10240), row stride KW
__device__ __half g_Wbf[(size_t)10240 * KW];

// =====================  PTX helpers (baseline ISA only)  ====================
__device__ __forceinline__ uint32_t smem_u32(const void* p) {
    uint32_t a;
    asm("{ .reg .u64 t; cvta.to.shared.u64 t, %1; cvt.u32.u64 %0, t; }" : "=r"(a) : "l"(p));
    return a;
}
__device__ __forceinline__ void cp_async16(uint32_t s, const void* g) {
    asm volatile("cp.async.cg.shared.global [%0], [%1], 16;" :: "r"(s), "l"(g));
}
__device__ __forceinline__ void cp_commit() {
    asm volatile("cp.async.commit_group;" ::: "memory");
}
template<int N_> __device__ __forceinline__ void cp_wait() {
    asm volatile("cp.async.wait_group %0;" :: "n"(N_) : "memory");
}
__device__ __forceinline__ void ldmatrix_x4(uint32_t* r, uint32_t addr) {
    asm volatile("ldmatrix.sync.aligned.m8n8.x4.shared.b16 {%0,%1,%2,%3}, [%4];"
                 : "=r"(r[0]), "=r"(r[1]), "=r"(r[2]), "=r"(r[3]) : "r"(addr));
}
__device__ __forceinline__ void ldmatrix_x4_trans(uint32_t* r, uint32_t addr) {
    asm volatile("ldmatrix.sync.aligned.m8n8.x4.trans.shared.b16 {%0,%1,%2,%3}, [%4];"
                 : "=r"(r[0]), "=r"(r[1]), "=r"(r[2]), "=r"(r[3]) : "r"(addr));
}
__device__ __forceinline__ void mma_16816(float* d, const uint32_t* a, const uint32_t* b) {
    asm volatile(
        "mma.sync.aligned.m16n8k16.row.col.f32.f16.f16.f32 "
        "{%0,%1,%2,%3}, {%4,%5,%6,%7}, {%8,%9}, {%0,%1,%2,%3};"
        : "+f"(d[0]), "+f"(d[1]), "+f"(d[2]), "+f"(d[3])
        : "r"(a[0]), "r"(a[1]), "r"(a[2]), "r"(a[3]), "r"(b[0]), "r"(b[1]));
}
__device__ __forceinline__ uint32_t pk_f16x2(float lo, float hi) {
    uint32_t d;
    asm("cvt.rn.f16x2.f32 %0, %1, %2;" : "=r"(d) : "f"(hi), "f"(lo));
    return d;
}
__device__ __forceinline__ float2 unpk_f16x2(uint32_t u) {
    __half2 h = *(__half2*)&u;
    return __half22float2(h);
}

// =====================  conversion kernels  =================================
// X[4096][4096] fp32 -> Y[4096][K2] fp16: [0,4096)=hi, [4096,8192)=lo (exact split)
__global__ __launch_bounds__(256) void convert_a_kernel(const float* __restrict__ X,
                                                        __half* __restrict__ Y) {
    int i = blockIdx.x * blockDim.x + threadIdx.x;
    int row = i >> 10;
    int col = (i & 1023) << 2;
    float4 v = ((const float4*)X)[i];
    __half hx = __float2half_rn(v.x);
    __half hy = __float2half_rn(v.y);
    __half hz = __float2half_rn(v.z);
    __half hw = __float2half_rn(v.w);
    __half lx = __float2half_rn(v.x - __half2float(hx));
    __half ly = __float2half_rn(v.y - __half2float(hy));
    __half lz = __float2half_rn(v.z - __half2float(hz));
    __half lw = __float2half_rn(v.w - __half2float(hw));
    size_t base = (size_t)row * K2 + col;
    ((__half2*)(Y + base))[0] = __halves2half2(hx, hy);
    ((__half2*)(Y + base))[1] = __halves2half2(hz, hw);
    ((__half2*)(Y + base + 4096))[0] = __halves2half2(lx, ly);
    ((__half2*)(Y + base + 4096))[1] = __halves2half2(lz, lw);
}

// W[K=4096][N] fp32 -> Y[N][KW] fp16 single, transposed
__global__ __launch_bounds__(256) void convert_w_kernel(const float* __restrict__ W,
                                                        __half* __restrict__ Y, int N) {
    __shared__ float t[32][33];
    int n0 = blockIdx.x * 32;
    int k0 = blockIdx.y * 32;
    int tx = threadIdx.x;
    int ty = threadIdx.y;
#pragma unroll
    for (int i = 0; i < 4; i++)
        t[ty + 8 * i][tx] = W[(size_t)(k0 + ty + 8 * i) * N + n0 + tx];
    __syncthreads();
#pragma unroll
    for (int i = 0; i < 4; i++) {
        int r = ty + 8 * i;
        Y[(size_t)(n0 + r) * KW + k0 + tx] = __float2half_rn(t[tx][r]);
    }
}

// =====================  RoPE table  =========================================
__global__ void rope_table_kernel() {
    int idx = blockIdx.x * blockDim.x + threadIdx.x;
    if (idx >= 2048 * 64) return;
    int p = idx >> 6;
    int i = idx & 63;
    double inv_d = exp(-((double)(2 * i) / (double)HD) * log(ROPE_THETA));
    float invf = (float)inv_d;
    float angf = (float)p * invf;          // fp32 product, as in the reference
    g_cos[idx] = (float)cos((double)angf);
    g_sin[idx] = (float)sin((double)angf);
}

// =====================  mma.sync fp16 GEMM  =================================
// CTA 128x128, 256 threads (8 warps, 4m x 2n), warp tile 32x64, BK=64, 2 stages.
// Stage = A-hi 16KB | A-lo 16KB | B 16KB (48KB). Both split terms per K-chunk,
// B staged once; B fragments held in regs across the A loop (8 LDSM / 32 MMA).
// MODE 0: C fp32 write. MODE 1: fused rope+scale+split epilogue to q/k/v bufs.
#define BKK 64
#define NST 2
#define STAGE_BYTES 49152
#define GEMM_SMEM (NST * STAGE_BYTES)

__device__ __forceinline__ void gemm_load_stage(
    const __half* __restrict__ A, const __half* __restrict__ Bt,
    int m0, int n0, int it, uint32_t st, int tid)
{
    int kk = it * BKK;
#pragma unroll
    for (int u = 0; u < 4; u++) {             // A-hi
        int f = u * 256 + tid;
        int r = f >> 3;
        int c = f & 7;
        uint32_t sw = (uint32_t)(c ^ (r & 7));
        cp_async16(st + (uint32_t)r * 128u + sw * 16u,
                   A + (size_t)(m0 + r) * K2 + kk + c * 8);
    }
#pragma unroll
    for (int u = 0; u < 4; u++) {             // A-lo
        int f = u * 256 + tid;
        int r = f >> 3;
        int c = f & 7;
        uint32_t sw = (uint32_t)(c ^ (r & 7));
        cp_async16(st + 16384u + (uint32_t)r * 128u + sw * 16u,
                   A + (size_t)(m0 + r) * K2 + 4096 + kk + c * 8);
    }
#pragma unroll
    for (int u = 0; u < 4; u++) {             // B
        int f = u * 256 + tid;
        int r = f >> 3;
        int c = f & 7;
        uint32_t sw = (uint32_t)(c ^ (r & 7));
        cp_async16(st + 32768u + (uint32_t)r * 128u + sw * 16u,
                   Bt + (size_t)(n0 + r) * KW + kk + c * 8);
    }
    cp_commit();
}

template<int MODE>
__global__ __launch_bounds__(256, 2) void gemm_f16_kernel(
    const __half* __restrict__ A, const __half* __restrict__ Bt,
    float* __restrict__ C, int N,
    __half* __restrict__ qh, __half* __restrict__ ql,
    __half* __restrict__ kh, __half* __restrict__ vh,
    const int* __restrict__ pos)
{
    extern __shared__ __align__(1024) char gsm[];
    const uint32_t sbase = smem_u32(gsm);
    const int tid  = threadIdx.x;
    const int wid  = tid >> 5;
    const int lane = tid & 31;

    const int m0 = blockIdx.x * 128;
    const int n0 = blockIdx.y * 128;
    const int wm = (wid >> 1) * 32;      // 4 warps along m
    const int wn = (wid & 1) * 64;       // 2 warps along n

    float acc[2][8][4];
#pragma unroll
    for (int i = 0; i < 2; i++)
#pragma unroll
        for (int j = 0; j < 8; j++)
#pragma unroll
            for (int e = 0; e < 4; e++) acc[i][j][e] = 0.f;

    const int iters = 64;   // 64 K-chunks of 64; both terms per chunk
    gemm_load_stage(A, Bt, m0, n0, 0, sbase + 0u * STAGE_BYTES, tid);
    gemm_load_stage(A, Bt, m0, n0, 1, sbase + 1u * STAGE_BYTES, tid);

    const int a_row_in16 = ((lane >> 3) & 1) * 8 + (lane & 7);
    const int a_cadd     = lane >> 4;
    const int b_sel      = lane >> 4;
    const int b_row8     = lane & 7;
    const int b_cs       = (lane >> 3) & 1;

    for (int it = 0; it < iters; it++) {
        cp_wait<1>();
        __syncthreads();

        uint32_t st = sbase + (uint32_t)(it & 1) * STAGE_BYTES;
        uint32_t sAh = st;
        uint32_t sAl = st + 16384u;
        uint32_t sB  = st + 32768u;

#pragma unroll
        for (int ks = 0; ks < 4; ks++) {
            int c0 = ks * 2;
            uint32_t bfr[4][4];
#pragma unroll
            for (int njp = 0; njp < 4; njp++) {
                int r  = wn + (njp * 2 + b_sel) * 8 + b_row8;
                int cc = c0 + b_cs;
                uint32_t addr = sB + (uint32_t)r * 128u + (uint32_t)((cc ^ (r & 7)) * 16);
                ldmatrix_x4(bfr[njp], addr);
            }
#pragma unroll
            for (int im = 0; im < 2; im++) {
                int r  = wm + im * 16 + a_row_in16;
                int cc = c0 + a_cadd;
                uint32_t aoff = (uint32_t)r * 128u + (uint32_t)((cc ^ (r & 7)) * 16);
                uint32_t afh[4], afl[4];
                ldmatrix_x4(afh, sAh + aoff);
                ldmatrix_x4(afl, sAl + aoff);
#pragma unroll
                for (int njp = 0; njp < 4; njp++) {
                    mma_16816(acc[im][2 * njp],     afh, bfr[njp]);
                    mma_16816(acc[im][2 * njp],     afl, bfr[njp]);
                    mma_16816(acc[im][2 * njp + 1], afh, bfr[njp] + 2);
                    mma_16816(acc[im][2 * njp + 1], afl, bfr[njp] + 2);
                }
            }
        }

        __syncthreads();     // all warps done with this buffer before refill
        if (it + 2 < iters)
            gemm_load_stage(A, Bt, m0, n0, it + 2, st, tid);
    }

    const int tg = lane >> 2;
    const int tc = lane & 3;

    if (MODE == 0) {
#pragma unroll
        for (int im = 0; im < 2; im++) {
#pragma unroll
            for (int jn = 0; jn < 8; jn++) {
                int row = m0 + wm + im * 16 + tg;
                int col = n0 + wn + jn * 8 + tc * 2;
                float2 v0 = make_float2(acc[im][jn][0], acc[im][jn][1]);
                float2 v1 = make_float2(acc[im][jn][2], acc[im][jn][3]);
                *(float2*)(C + (size_t)row * N + col) = v0;
                *(float2*)(C + (size_t)(row + 8) * N + col) = v1;
            }
        }
        return;
    }

    // MODE 1: fused rope + scale + fp16 split epilogue (QKV projection)
    const bool isq = (n0 < 4096);
    const bool isk = (n0 >= 4096) && (n0 < 5120);
#pragma unroll
    for (int im = 0; im < 2; im++) {
#pragma unroll
        for (int r2 = 0; r2 < 2; r2++) {
            int t = m0 + wm + im * 16 + tg + r2 * 8;
            int p = pos[t];
#pragma unroll
            for (int jn = 0; jn < 8; jn++) {
                int col = n0 + wn + jn * 8 + tc * 2;
                float a = acc[im][jn][2 * r2 + 0];
                float b = acc[im][jn][2 * r2 + 1];
                if (isq || isk) {
                    int i0 = (col & 127) >> 1;
                    float c = g_cos[p * 64 + i0];
                    float s = g_sin[p * 64 + i0];
                    float na = a * c - b * s;
                    float nb = a * s + b * c;
                    a = na; b = nb;
                }
                if (isq) {
                    a *= QSCALE; b *= QSCALE;
                    __half ha = __float2half_rn(a), hb = __float2half_rn(b);
                    __half la = __float2half_rn(a - __half2float(ha));
                    __half lb = __float2half_rn(b - __half2float(hb));
                    *(__half2*)(qh + (size_t)t * 4096 + col) = __halves2half2(ha, hb);
                    *(__half2*)(ql + (size_t)t * 4096 + col) = __halves2half2(la, lb);
                } else if (isk) {
                    __half ha = __float2half_rn(a), hb = __float2half_rn(b);
                    *(__half2*)(kh + (size_t)t * 1024 + (col - 4096)) = __halves2half2(ha, hb);
                } else {
                    __half ha = __float2half_rn(a), hb = __float2half_rn(b);
                    *(__half2*)(vh + (size_t)t * 1024 + (col - 5120)) = __halves2half2(ha, hb);
                }
            }
        }
    }
}

// =====================  Flash attention (mma.sync fp16, 2-term)  ============
// CTA: 64 q-rows x 64 kv, 4 warps. Tiles: Qh(0) Ql(16K) Kh(32K) Vh(48K), mask @64K.
// Epilogue writes fp16 hi|lo split directly into the out-proj A operand.
#define FL_SMEM (4 * 16384 + 512)

__global__ __launch_bounds__(128) void flash_mma_kernel(
    const __half* __restrict__ Qh, const __half* __restrict__ Ql,
    const __half* __restrict__ Kh, const __half* __restrict__ Vh,
    const float* __restrict__ amask, __half* __restrict__ Obf)
{
    extern __shared__ __align__(1024) char fsm[];
    const uint32_t sb = smem_u32(fsm);
    float* sMask = (float*)(fsm + 65536);

    const int tid  = threadIdx.x;
    const int warp = tid >> 5;
    const int lane = tid & 31;
    const int tg   = lane >> 2;
    const int tc   = lane & 3;
    const int qt   = (S_ / 64 - 1) - blockIdx.x;   // long tiles first
    const int h    = blockIdx.y;
    const int b    = blockIdx.z;
    const int kvh  = h >> 2;

    // ---- load Q tiles (hi, lo) ----
    {
        const __half* qs[2] = {Qh, Ql};
#pragma unroll
        for (int t = 0; t < 16; t++) {
            int f = t * 128 + tid;
            int tile = t >> 3;
            int ft = f & 1023;
            int r = ft >> 4, c = ft & 15;
            uint32_t dst = sb + (uint32_t)tile * 16384u + (uint32_t)r * 256u +
                           (uint32_t)((c ^ (r & 7)) * 16);
            cp_async16(dst, qs[tile] + (size_t)(b * S_ + qt * 64 + r) * D_ + h * HD + c * 8);
        }
        cp_commit();
    }

    float acc_o[16][4];
#pragma unroll
    for (int i = 0; i < 16; i++)
#pragma unroll
        for (int e = 0; e < 4; e++) acc_o[i][e] = 0.f;
    float m0 = -INFINITY, m1 = -INFINITY, l0 = 0.f, l1 = 0.f;

    const int a_r16  = ((lane >> 3) & 1) * 8 + (lane & 7);
    const int a_cs   = lane >> 4;
    const int b_nsel = lane >> 4;
    const int b_row8 = lane & 7;
    const int b_cs   = (lane >> 3) & 1;
    const int v_half = (lane >> 3) & 1;
    const int v_sel  = lane >> 4;
    const int v_row7 = lane & 7;

    for (int kt = 0; kt <= qt; kt++) {
        if (kt) __syncthreads();     // all warps done reading prev K/V
        // ---- load K tile then V tile, separate commit groups ----
        {
#pragma unroll
            for (int t = 0; t < 8; t++) {
                int f = t * 128 + tid;
                int r = f >> 4, c = f & 15;
                uint32_t dst = sb + 32768u + (uint32_t)r * 256u +
                               (uint32_t)((c ^ (r & 7)) * 16);
                cp_async16(dst, Kh + (size_t)(b * S_ + kt * 64 + r) * KVDIM + kvh * HD + c * 8);
            }
            cp_commit();
#pragma unroll
            for (int t = 0; t < 8; t++) {
                int f = t * 128 + tid;
                int r = f >> 4, c = f & 15;
                uint32_t dst = sb + 49152u + (uint32_t)r * 256u +
                               (uint32_t)((c ^ (r & 7)) * 16);
                cp_async16(dst, Vh + (size_t)(b * S_ + kt * 64 + r) * KVDIM + kvh * HD + c * 8);
            }
            cp_commit();
        }
        if (tid < 64) sMask[tid] = amask[b * S_ + kt * 64 + tid];
        cp_wait<1>();                 // K (and Q on first iter) ready; V in flight
        __syncthreads();

        // ---- S = Q K^T (qh*kh + ql*kh) ----
        float accs[8][4];
#pragma unroll
        for (int nj = 0; nj < 8; nj++)
#pragma unroll
            for (int e = 0; e < 4; e++) accs[nj][e] = 0.f;

#pragma unroll
        for (int kc = 0; kc < 8; kc++) {
            uint32_t qh4[4], ql4[4];
            {
                int r = warp * 16 + a_r16;
                int cc = kc * 2 + a_cs;
                uint32_t off = (uint32_t)r * 256u + (uint32_t)((cc ^ (r & 7)) * 16);
                ldmatrix_x4(qh4, sb + off);
                ldmatrix_x4(ql4, sb + 16384u + off);
            }
#pragma unroll
            for (int njp = 0; njp < 4; njp++) {
                uint32_t kh4[4];
                int r = (njp * 2 + b_nsel) * 8 + b_row8;
                int cc = kc * 2 + b_cs;
                uint32_t off = (uint32_t)r * 256u + (uint32_t)((cc ^ (r & 7)) * 16);
                ldmatrix_x4(kh4, sb + 32768u + off);
                mma_16816(accs[2 * njp],     qh4, kh4);
                mma_16816(accs[2 * njp],     ql4, kh4);
                mma_16816(accs[2 * njp + 1], qh4, kh4 + 2);
                mma_16816(accs[2 * njp + 1], ql4, kh4 + 2);
            }
        }

        // ---- mask + online softmax ----
        const bool diag = (kt == qt);
        float mx0 = -INFINITY, mx1 = -INFINITY;
#pragma unroll
        for (int nj = 0; nj < 8; nj++) {
#pragma unroll
            for (int e = 0; e < 4; e++) {
                int kvl = nj * 8 + 2 * tc + (e & 1);
                bool valid = sMask[kvl] > 0.f;
                if (diag) {
                    int qloc = warp * 16 + tg + ((e >> 1) ? 8 : 0);
                    valid = valid && (kvl <= qloc);
                }
                float s = valid ? accs[nj][e] : -1e30f;
                accs[nj][e] = s;
                if (e < 2) mx0 = fmaxf(mx0, s); else mx1 = fmaxf(mx1, s);
            }
        }
        mx0 = fmaxf(mx0, __shfl_xor_sync(0xffffffffu, mx0, 1));
        mx0 = fmaxf(mx0, __shfl_xor_sync(0xffffffffu, mx0, 2));
        mx1 = fmaxf(mx1, __shfl_xor_sync(0xffffffffu, mx1, 1));
        mx1 = fmaxf(mx1, __shfl_xor_sync(0xffffffffu, mx1, 2));

        float mn0 = fmaxf(m0, mx0), mn1 = fmaxf(m1, mx1);
        float cr0 = __expf(m0 - mn0), cr1 = __expf(m1 - mn1);
        m0 = mn0; m1 = mn1;

        float s0 = 0.f, s1 = 0.f;
#pragma unroll
        for (int nj = 0; nj < 8; nj++) {
#pragma unroll
            for (int e = 0; e < 4; e++) {
                float p = __expf(accs[nj][e] - ((e < 2) ? m0 : m1));
                accs[nj][e] = p;
                if (e < 2) s0 += p; else s1 += p;
            }
        }
        s0 += __shfl_xor_sync(0xffffffffu, s0, 1);
        s0 += __shfl_xor_sync(0xffffffffu, s0, 2);
        s1 += __shfl_xor_sync(0xffffffffu, s1, 1);
        s1 += __shfl_xor_sync(0xffffffffu, s1, 2);
        l0 = l0 * cr0 + s0;
        l1 = l1 * cr1 + s1;

#pragma unroll
        for (int nd = 0; nd < 16; nd++) {
            acc_o[nd][0] *= cr0; acc_o[nd][1] *= cr0;
            acc_o[nd][2] *= cr1; acc_o[nd][3] *= cr1;
        }

        cp_wait<0>();                 // V now ready
        __syncthreads();

        // ---- O += P V (ph*vh + pl*vh) ----
#pragma unroll
        for (int kc2 = 0; kc2 < 4; kc2++) {
            float* p0 = accs[2 * kc2];
            float* p1 = accs[2 * kc2 + 1];
            uint32_t ah[4], al[4];
            ah[0] = pk_f16x2(p0[0], p0[1]);
            ah[1] = pk_f16x2(p0[2], p0[3]);
            ah[2] = pk_f16x2(p1[0], p1[1]);
            ah[3] = pk_f16x2(p1[2], p1[3]);
            {
                float2 f;
                f = unpk_f16x2(ah[0]); al[0] = pk_f16x2(p0[0] - f.x, p0[1] - f.y);
                f = unpk_f16x2(ah[1]); al[1] = pk_f16x2(p0[2] - f.x, p0[3] - f.y);
                f = unpk_f16x2(ah[2]); al[2] = pk_f16x2(p1[0] - f.x, p1[1] - f.y);
                f = unpk_f16x2(ah[3]); al[3] = pk_f16x2(p1[2] - f.x, p1[3] - f.y);
            }
            int vr = kc2 * 16 + v_half * 8 + v_row7;
#pragma unroll
            for (int ndp = 0; ndp < 8; ndp++) {
                int chunk = ndp * 2 + v_sel;
                uint32_t off = (uint32_t)vr * 256u + (uint32_t)((chunk ^ (vr & 7)) * 16);
                uint32_t bh4[4];
                ldmatrix_x4_trans(bh4, sb + 49152u + off);
                mma_16816(acc_o[2 * ndp],     ah, bh4);
                mma_16816(acc_o[2 * ndp],     al, bh4);
                mma_16816(acc_o[2 * ndp + 1], ah, bh4 + 2);
                mma_16816(acc_o[2 * ndp + 1], al, bh4 + 2);
            }
        }
    }

    // ---- normalize + split-fp16 write into out-proj A operand ----
    float inv0 = 1.f / l0, inv1 = 1.f / l1;
    int row0 = b * S_ + qt * 64 + warp * 16 + tg;
#pragma unroll
    for (int nd = 0; nd < 16; nd++) {
        int col = h * HD + nd * 8 + 2 * tc;
        float x0 = acc_o[nd][0] * inv0, x1 = acc_o[nd][1] * inv0;
        float x2 = acc_o[nd][2] * inv1, x3 = acc_o[nd][3] * inv1;
        __half h0 = __float2half_rn(x0), h1 = __float2half_rn(x1);
        __half h2 = __float2half_rn(x2), h3 = __float2half_rn(x3);
        __half e0 = __float2half_rn(x0 - __half2float(h0));
        __half e1 = __float2half_rn(x1 - __half2float(h1));
        __half e2 = __float2half_rn(x2 - __half2float(h2));
        __half e3 = __float2half_rn(x3 - __half2float(h3));
        *(__half2*)(Obf + (size_t)row0 * K2 + col)              = __halves2half2(h0, h1);
        *(__half2*)(Obf + (size_t)row0 * K2 + 4096 + col)       = __halves2half2(e0, e1);
        *(__half2*)(Obf + (size_t)(row0 + 8) * K2 + col)        = __halves2half2(h2, h3);
        *(__half2*)(Obf + (size_t)(row0 + 8) * K2 + 4096 + col) = __halves2half2(e2, e3);
    }
}

// =====================  launch  =============================================
extern "C" void kernel_launch(void* const* d_in, const int* in_sizes, int n_in,
                              void* d_out, int out_size)
{
    const float* x     = (const float*)d_in[0];
    const float* amask = (const float*)d_in[1];
    const int*   pos   = (const int*)  d_in[2];
    const float* wq    = (const float*)d_in[3];
    const float* wk    = (const float*)d_in[4];
    const float* wv    = (const float*)d_in[5];
    const float* wo    = (const float*)d_in[6];
    float* out = (float*)d_out;

    __half *abf, *obf, *wbf;
    cudaGetSymbolAddress((void**)&abf, g_Abf);
    cudaGetSymbolAddress((void**)&obf, g_Obf);
    cudaGetSymbolAddress((void**)&wbf, g_Wbf);

    __half* wqkv_h = wbf;                              // rows [0,6144)
    __half* wo_h   = wbf + (size_t)QKVN * KW;          // rows [0,4096)

    // buffer layout inside g_Abf
    const size_t XSZ = (size_t)MTOK * K2;     // 32M halves: x split
    const size_t QSZ = (size_t)MTOK * D_;     // 16M
    const size_t KSZ = (size_t)MTOK * KVDIM;  // 4M
    __half* xs = abf;
    __half* qh = abf + XSZ;
    __half* ql = qh + QSZ;
    __half* kh = ql + QSZ;
    __half* vh = kh + KSZ;

    cudaFuncSetAttribute(gemm_f16_kernel<1>, cudaFuncAttributeMaxDynamicSharedMemorySize, GEMM_SMEM);
    cudaFuncSetAttribute(gemm_f16_kernel<0>, cudaFuncAttributeMaxDynamicSharedMemorySize, GEMM_SMEM);
    cudaFuncSetAttribute(flash_mma_kernel, cudaFuncAttributeMaxDynamicSharedMemorySize, FL_SMEM);

    // RoPE tables (2048 positions)
    rope_table_kernel<<<(2048 * 64) / 256, 256>>>();

    // Conversions: x split fp16, weights single fp16 transposed
    convert_a_kernel<<<(MTOK * D_ / 4) / 256, 256>>>(x, xs);
    convert_w_kernel<<<dim3(D_ / 32,    D_ / 32), dim3(32, 8)>>>(wq, wqkv_h, D_);
    convert_w_kernel<<<dim3(KVDIM / 32, D_ / 32), dim3(32, 8)>>>(wk, wqkv_h + (size_t)4096 * KW, KVDIM);
    convert_w_kernel<<<dim3(KVDIM / 32, D_ / 32), dim3(32, 8)>>>(wv, wqkv_h + (size_t)5120 * KW, KVDIM);
    convert_w_kernel<<<dim3(D_ / 32,    D_ / 32), dim3(32, 8)>>>(wo, wo_h, D_);

    // Fused QKV projection + rope + scale + fp16 split (one GEMM, N=6144)
    gemm_f16_kernel<1><<<dim3(MTOK / 128, QKVN / 128), 256, GEMM_SMEM>>>(
        xs, wqkv_h, nullptr, QKVN, qh, ql, kh, vh, pos);

    // Attention (tensor-core flash) -> writes split fp16 out-proj operand
    flash_mma_kernel<<<dim3(S_ / 64, NH, B_), 128, FL_SMEM>>>(qh, ql, kh, vh, amask, obf);

    // Output projection (2-term split A, fp32 out)
    gemm_f16_kernel<0><<<dim3(MTOK / 128, D_ / 128), 256, GEMM_SMEM>>>(
        obf, wo_h, out, D_, nullptr, nullptr, nullptr, nullptr, nullptr);
}

// round 17
// speedup vs baseline: 1.2112x; 1.0074x over previous
#include <cuda_runtime.h>
#include <cuda_fp16.h>
#include <cstdint>
#include <math.h>

// Problem constants
#define B_    2
#define S_    2048
#define D_    4096
#define NH    32
#define NKV   8
#define HD    128
#define MTOK  (B_*S_)          // 4096 tokens
#define KVDIM (NKV*HD)         // 1024
#define QKVN  (D_ + 2*KVDIM)   // 6144 fused projection width
#define K2    8192             // split A operand: [hi|lo] fp16
#define KW    4096             // W operand: single fp16
#define QSCALE 0.08838834764831845f
#define ROPE_THETA 500000.0

// -------------------- scratch (device globals; no allocs allowed) -----------
__device__ float g_cos[2048 * 64];
__device__ float g_sin[2048 * 64];
// x split (32M halves) | qh (16M) | ql (16M) | kh (4M) | vh (4M)  = 72M halves
__device__ __half g_Abf[(size_t)MTOK * 18432];
// attention output, split fp16 [t][K2] (out-proj A operand)
__device__ __half g_Obf[(size_t)MTOK * K2];
// weights single fp16: [qkv rows 0..6144) | wo rows 6144..10240), row stride KW
__device__ __half g_Wbf[(size_t)10240 * KW];

// =====================  PTX helpers (baseline ISA only)  ====================
__device__ __forceinline__ uint32_t smem_u32(const void* p) {
    uint32_t a;
    asm("{ .reg .u64 t; cvta.to.shared.u64 t, %1; cvt.u32.u64 %0, t; }" : "=r"(a) : "l"(p));
    return a;
}
__device__ __forceinline__ void cp_async16(uint32_t s, const void* g) {
    asm volatile("cp.async.cg.shared.global [%0], [%1], 16;" :: "r"(s), "l"(g));
}
__device__ __forceinline__ void cp_commit() {
    asm volatile("cp.async.commit_group;" ::: "memory");
}
template<int N_> __device__ __forceinline__ void cp_wait() {
    asm volatile("cp.async.wait_group %0;" :: "n"(N_) : "memory");
}
__device__ __forceinline__ void ldmatrix_x4(uint32_t* r, uint32_t addr) {
    asm volatile("ldmatrix.sync.aligned.m8n8.x4.shared.b16 {%0,%1,%2,%3}, [%4];"
                 : "=r"(r[0]), "=r"(r[1]), "=r"(r[2]), "=r"(r[3]) : "r"(addr));
}
__device__ __forceinline__ void ldmatrix_x4_trans(uint32_t* r, uint32_t addr) {
    asm volatile("ldmatrix.sync.aligned.m8n8.x4.trans.shared.b16 {%0,%1,%2,%3}, [%4];"
                 : "=r"(r[0]), "=r"(r[1]), "=r"(r[2]), "=r"(r[3]) : "r"(addr));
}
__device__ __forceinline__ void mma_16816(float* d, const uint32_t* a, const uint32_t* b) {
    asm volatile(
        "mma.sync.aligned.m16n8k16.row.col.f32.f16.f16.f32 "
        "{%0,%1,%2,%3}, {%4,%5,%6,%7}, {%8,%9}, {%0,%1,%2,%3};"
        : "+f"(d[0]), "+f"(d[1]), "+f"(d[2]), "+f"(d[3])
        : "r"(a[0]), "r"(a[1]), "r"(a[2]), "r"(a[3]), "r"(b[0]), "r"(b[1]));
}
__device__ __forceinline__ uint32_t pk_f16x2(float lo, float hi) {
    uint32_t d;
    asm("cvt.rn.f16x2.f32 %0, %1, %2;" : "=r"(d) : "f"(hi), "f"(lo));
    return d;
}
__device__ __forceinline__ float2 unpk_f16x2(uint32_t u) {
    __half2 h = *(__half2*)&u;
    return __half22float2(h);
}

// =====================  conversion kernels  =================================
// X[4096][4096] fp32 -> Y[4096][K2] fp16: [0,4096)=hi, [4096,8192)=lo (exact split)
__global__ __launch_bounds__(256) void convert_a_kernel(const float* __restrict__ X,
                                                        __half* __restrict__ Y) {
    int i = blockIdx.x * blockDim.x + threadIdx.x;
    int row = i >> 10;
    int col = (i & 1023) << 2;
    float4 v = ((const float4*)X)[i];
    __half hx = __float2half_rn(v.x);
    __half hy = __float2half_rn(v.y);
    __half hz = __float2half_rn(v.z);
    __half hw = __float2half_rn(v.w);
    __half lx = __float2half_rn(v.x - __half2float(hx));
    __half ly = __float2half_rn(v.y - __half2float(hy));
    __half lz = __float2half_rn(v.z - __half2float(hz));
    __half lw = __float2half_rn(v.w - __half2float(hw));
    size_t base = (size_t)row * K2 + col;
    ((__half2*)(Y + base))[0] = __halves2half2(hx, hy);
    ((__half2*)(Y + base))[1] = __halves2half2(hz, hw);
    ((__half2*)(Y + base + 4096))[0] = __halves2half2(lx, ly);
    ((__half2*)(Y + base + 4096))[1] = __halves2half2(lz, lw);
}

// W[K=4096][N] fp32 -> Y[N][KW] fp16 single, transposed
__global__ __launch_bounds__(256) void convert_w_kernel(const float* __restrict__ W,
                                                        __half* __restrict__ Y, int N) {
    __shared__ float t[32][33];
    int n0 = blockIdx.x * 32;
    int k0 = blockIdx.y * 32;
    int tx = threadIdx.x;
    int ty = threadIdx.y;
#pragma unroll
    for (int i = 0; i < 4; i++)
        t[ty + 8 * i][tx] = W[(size_t)(k0 + ty + 8 * i) * N + n0 + tx];
    __syncthreads();
#pragma unroll
    for (int i = 0; i < 4; i++) {
        int r = ty + 8 * i;
        Y[(size_t)(n0 + r) * KW + k0 + tx] = __float2half_rn(t[tx][r]);
    }
}

// =====================  RoPE table  =========================================
__global__ void rope_table_kernel() {
    int idx = blockIdx.x * blockDim.x + threadIdx.x;
    if (idx >= 2048 * 64) return;
    int p = idx >> 6;
    int i = idx & 63;
    double inv_d = exp(-((double)(2 * i) / (double)HD) * log(ROPE_THETA));
    float invf = (float)inv_d;
    float angf = (float)p * invf;          // fp32 product, as in the reference
    g_cos[idx] = (float)cos((double)angf);
    g_sin[idx] = (float)sin((double)angf);
}

// =====================  mma.sync fp16 GEMM  =================================
// CTA 128x128, 256 threads (8 warps, 4m x 2n), warp tile 32x64, BK=64, 2 stages.
// Stage = A-hi 16KB | A-lo 16KB | B 16KB (48KB). Both split terms per K-chunk,
// B staged once; B fragments held in regs across the A loop.
// MODE 0: C fp32 write. MODE 1: fused rope+scale+split epilogue to q/k/v bufs.
#define BKK 64
#define NST 2
#define STAGE_BYTES 49152
#define GEMM_SMEM (NST * STAGE_BYTES)

__device__ __forceinline__ void gemm_load_stage(
    const __half* __restrict__ A, const __half* __restrict__ Bt,
    int m0, int n0, int it, uint32_t st, int tid)
{
    int kk = it * BKK;
#pragma unroll
    for (int u = 0; u < 4; u++) {             // A-hi
        int f = u * 256 + tid;
        int r = f >> 3;
        int c = f & 7;
        uint32_t sw = (uint32_t)(c ^ (r & 7));
        cp_async16(st + (uint32_t)r * 128u + sw * 16u,
                   A + (size_t)(m0 + r) * K2 + kk + c * 8);
    }
#pragma unroll
    for (int u = 0; u < 4; u++) {             // A-lo
        int f = u * 256 + tid;
        int r = f >> 3;
        int c = f & 7;
        uint32_t sw = (uint32_t)(c ^ (r & 7));
        cp_async16(st + 16384u + (uint32_t)r * 128u + sw * 16u,
                   A + (size_t)(m0 + r) * K2 + 4096 + kk + c * 8);
    }
#pragma unroll
    for (int u = 0; u < 4; u++) {             // B
        int f = u * 256 + tid;
        int r = f >> 3;
        int c = f & 7;
        uint32_t sw = (uint32_t)(c ^ (r & 7));
        cp_async16(st + 32768u + (uint32_t)r * 128u + sw * 16u,
                   Bt + (size_t)(n0 + r) * KW + kk + c * 8);
    }
    cp_commit();
}

template<int MODE>
__global__ __launch_bounds__(256, 2) void gemm_f16_kernel(
    const __half* __restrict__ A, const __half* __restrict__ Bt,
    float* __restrict__ C, int N,
    __half* __restrict__ qh, __half* __restrict__ ql,
    __half* __restrict__ kh, __half* __restrict__ vh,
    const int* __restrict__ pos)
{
    extern __shared__ __align__(1024) char gsm[];
    const uint32_t sbase = smem_u32(gsm);
    const int tid  = threadIdx.x;
    const int wid  = tid >> 5;
    const int lane = tid & 31;

    const int m0 = blockIdx.x * 128;
    const int n0 = blockIdx.y * 128;
    const int wm = (wid >> 1) * 32;      // 4 warps along m
    const int wn = (wid & 1) * 64;       // 2 warps along n

    float acc[2][8][4];
#pragma unroll
    for (int i = 0; i < 2; i++)
#pragma unroll
        for (int j = 0; j < 8; j++)
#pragma unroll
            for (int e = 0; e < 4; e++) acc[i][j][e] = 0.f;

    const int iters = 64;   // 64 K-chunks of 64; both terms per chunk
    gemm_load_stage(A, Bt, m0, n0, 0, sbase + 0u * STAGE_BYTES, tid);
    gemm_load_stage(A, Bt, m0, n0, 1, sbase + 1u * STAGE_BYTES, tid);

    const int a_row_in16 = ((lane >> 3) & 1) * 8 + (lane & 7);
    const int a_cadd     = lane >> 4;
    const int b_sel      = lane >> 4;
    const int b_row8     = lane & 7;
    const int b_cs       = (lane >> 3) & 1;

    for (int it = 0; it < iters; it++) {
        cp_wait<1>();
        __syncthreads();

        uint32_t st = sbase + (uint32_t)(it & 1) * STAGE_BYTES;
        uint32_t sAh = st;
        uint32_t sAl = st + 16384u;
        uint32_t sB  = st + 32768u;

#pragma unroll
        for (int ks = 0; ks < 4; ks++) {
            int c0 = ks * 2;
            uint32_t bfr[4][4];
#pragma unroll
            for (int njp = 0; njp < 4; njp++) {
                int r  = wn + (njp * 2 + b_sel) * 8 + b_row8;
                int cc = c0 + b_cs;
                uint32_t addr = sB + (uint32_t)r * 128u + (uint32_t)((cc ^ (r & 7)) * 16);
                ldmatrix_x4(bfr[njp], addr);
            }
#pragma unroll
            for (int im = 0; im < 2; im++) {
                int r  = wm + im * 16 + a_row_in16;
                int cc = c0 + a_cadd;
                uint32_t aoff = (uint32_t)r * 128u + (uint32_t)((cc ^ (r & 7)) * 16);
                uint32_t afh[4], afl[4];
                ldmatrix_x4(afh, sAh + aoff);
                ldmatrix_x4(afl, sAl + aoff);
#pragma unroll
                for (int njp = 0; njp < 4; njp++) {
                    mma_16816(acc[im][2 * njp],     afh, bfr[njp]);
                    mma_16816(acc[im][2 * njp],     afl, bfr[njp]);
                    mma_16816(acc[im][2 * njp + 1], afh, bfr[njp] + 2);
                    mma_16816(acc[im][2 * njp + 1], afl, bfr[njp] + 2);
                }
            }
        }

        __syncthreads();     // all warps done with this buffer before refill
        if (it + 2 < iters)
            gemm_load_stage(A, Bt, m0, n0, it + 2, st, tid);
    }

    const int tg = lane >> 2;
    const int tc = lane & 3;

    if (MODE == 0) {
#pragma unroll
        for (int im = 0; im < 2; im++) {
#pragma unroll
            for (int jn = 0; jn < 8; jn++) {
                int row = m0 + wm + im * 16 + tg;
                int col = n0 + wn + jn * 8 + tc * 2;
                float2 v0 = make_float2(acc[im][jn][0], acc[im][jn][1]);
                float2 v1 = make_float2(acc[im][jn][2], acc[im][jn][3]);
                *(float2*)(C + (size_t)row * N + col) = v0;
                *(float2*)(C + (size_t)(row + 8) * N + col) = v1;
            }
        }
        return;
    }

    // MODE 1: fused rope + scale + fp16 split epilogue (QKV projection)
    const bool isq = (n0 < 4096);
    const bool isk = (n0 >= 4096) && (n0 < 5120);
#pragma unroll
    for (int im = 0; im < 2; im++) {
#pragma unroll
        for (int r2 = 0; r2 < 2; r2++) {
            int t = m0 + wm + im * 16 + tg + r2 * 8;
            int p = pos[t];
#pragma unroll
            for (int jn = 0; jn < 8; jn++) {
                int col = n0 + wn + jn * 8 + tc * 2;
                float a = acc[im][jn][2 * r2 + 0];
                float b = acc[im][jn][2 * r2 + 1];
                if (isq || isk) {
                    int i0 = (col & 127) >> 1;
                    float c = g_cos[p * 64 + i0];
                    float s = g_sin[p * 64 + i0];
                    float na = a * c - b * s;
                    float nb = a * s + b * c;
                    a = na; b = nb;
                }
                if (isq) {
                    a *= QSCALE; b *= QSCALE;
                    __half ha = __float2half_rn(a), hb = __float2half_rn(b);
                    __half la = __float2half_rn(a - __half2float(ha));
                    __half lb = __float2half_rn(b - __half2float(hb));
                    *(__half2*)(qh + (size_t)t * 4096 + col) = __halves2half2(ha, hb);
                    *(__half2*)(ql + (size_t)t * 4096 + col) = __halves2half2(la, lb);
                } else if (isk) {
                    __half ha = __float2half_rn(a), hb = __float2half_rn(b);
                    *(__half2*)(kh + (size_t)t * 1024 + (col - 4096)) = __halves2half2(ha, hb);
                } else {
                    __half ha = __float2half_rn(a), hb = __float2half_rn(b);
                    *(__half2*)(vh + (size_t)t * 1024 + (col - 5120)) = __halves2half2(ha, hb);
                }
            }
        }
    }
}

// =====================  Flash attention (mma.sync fp16, 2-term)  ============
#define FL_SMEM (4 * 16384 + 512)

__global__ __launch_bounds__(128) void flash_mma_kernel(
    const __half* __restrict__ Qh, const __half* __restrict__ Ql,
    const __half* __restrict__ Kh, const __half* __restrict__ Vh,
    const float* __restrict__ amask, __half* __restrict__ Obf)
{
    extern __shared__ __align__(1024) char fsm[];
    const uint32_t sb = smem_u32(fsm);
    float* sMask = (float*)(fsm + 65536);

    const int tid  = threadIdx.x;
    const int warp = tid >> 5;
    const int lane = tid & 31;
    const int tg   = lane >> 2;
    const int tc   = lane & 3;
    const int qt   = (S_ / 64 - 1) - blockIdx.x;   // long tiles first
    const int h    = blockIdx.y;
    const int b    = blockIdx.z;
    const int kvh  = h >> 2;

    {
        const __half* qs[2] = {Qh, Ql};
#pragma unroll
        for (int t = 0; t < 16; t++) {
            int f = t * 128 + tid;
            int tile = t >> 3;
            int ft = f & 1023;
            int r = ft >> 4, c = ft & 15;
            uint32_t dst = sb + (uint32_t)tile * 16384u + (uint32_t)r * 256u +
                           (uint32_t)((c ^ (r & 7)) * 16);
            cp_async16(dst, qs[tile] + (size_t)(b * S_ + qt * 64 + r) * D_ + h * HD + c * 8);
        }
        cp_commit();
    }

    float acc_o[16][4];
#pragma unroll
    for (int i = 0; i < 16; i++)
#pragma unroll
        for (int e = 0; e < 4; e++) acc_o[i][e] = 0.f;
    float m0 = -INFINITY, m1 = -INFINITY, l0 = 0.f, l1 = 0.f;

    const int a_r16  = ((lane >> 3) & 1) * 8 + (lane & 7);
    const int a_cs   = lane >> 4;
    const int b_nsel = lane >> 4;
    const int b_row8 = lane & 7;
    const int b_cs   = (lane >> 3) & 1;
    const int v_half = (lane >> 3) & 1;
    const int v_sel  = lane >> 4;
    const int v_row7 = lane & 7;

    for (int kt = 0; kt <= qt; kt++) {
        if (kt) __syncthreads();
        {
#pragma unroll
            for (int t = 0; t < 8; t++) {
                int f = t * 128 + tid;
                int r = f >> 4, c = f & 15;
                uint32_t dst = sb + 32768u + (uint32_t)r * 256u +
                               (uint32_t)((c ^ (r & 7)) * 16);
                cp_async16(dst, Kh + (size_t)(b * S_ + kt * 64 + r) * KVDIM + kvh * HD + c * 8);
            }
            cp_commit();
#pragma unroll
            for (int t = 0; t < 8; t++) {
                int f = t * 128 + tid;
                int r = f >> 4, c = f & 15;
                uint32_t dst = sb + 49152u + (uint32_t)r * 256u +
                               (uint32_t)((c ^ (r & 7)) * 16);
                cp_async16(dst, Vh + (size_t)(b * S_ + kt * 64 + r) * KVDIM + kvh * HD + c * 8);
            }
            cp_commit();
        }
        if (tid < 64) sMask[tid] = amask[b * S_ + kt * 64 + tid];
        cp_wait<1>();
        __syncthreads();

        float accs[8][4];
#pragma unroll
        for (int nj = 0; nj < 8; nj++)
#pragma unroll
            for (int e = 0; e < 4; e++) accs[nj][e] = 0.f;

#pragma unroll
        for (int kc = 0; kc < 8; kc++) {
            uint32_t qh4[4], ql4[4];
            {
                int r = warp * 16 + a_r16;
                int cc = kc * 2 + a_cs;
                uint32_t off = (uint32_t)r * 256u + (uint32_t)((cc ^ (r & 7)) * 16);
                ldmatrix_x4(qh4, sb + off);
                ldmatrix_x4(ql4, sb + 16384u + off);
            }
#pragma unroll
            for (int njp = 0; njp < 4; njp++) {
                uint32_t kh4[4];
                int r = (njp * 2 + b_nsel) * 8 + b_row8;
                int cc = kc * 2 + b_cs;
                uint32_t off = (uint32_t)r * 256u + (uint32_t)((cc ^ (r & 7)) * 16);
                ldmatrix_x4(kh4, sb + 32768u + off);
                mma_16816(accs[2 * njp],     qh4, kh4);
                mma_16816(accs[2 * njp],     ql4, kh4);
                mma_16816(accs[2 * njp + 1], qh4, kh4 + 2);
                mma_16816(accs[2 * njp + 1], ql4, kh4 + 2);
            }
        }

        const bool diag = (kt == qt);
        float mx0 = -INFINITY, mx1 = -INFINITY;
#pragma unroll
        for (int nj = 0; nj < 8; nj++) {
#pragma unroll
            for (int e = 0; e < 4; e++) {
                int kvl = nj * 8 + 2 * tc + (e & 1);
                bool valid = sMask[kvl] > 0.f;
                if (diag) {
                    int qloc = warp * 16 + tg + ((e >> 1) ? 8 : 0);
                    valid = valid && (kvl <= qloc);
                }
                float s = valid ? accs[nj][e] : -1e30f;
                accs[nj][e] = s;
                if (e < 2) mx0 = fmaxf(mx0, s); else mx1 = fmaxf(mx1, s);
            }
        }
        mx0 = fmaxf(mx0, __shfl_xor_sync(0xffffffffu, mx0, 1));
        mx0 = fmaxf(mx0, __shfl_xor_sync(0xffffffffu, mx0, 2));
        mx1 = fmaxf(mx1, __shfl_xor_sync(0xffffffffu, mx1, 1));
        mx1 = fmaxf(mx1, __shfl_xor_sync(0xffffffffu, mx1, 2));

        float mn0 = fmaxf(m0, mx0), mn1 = fmaxf(m1, mx1);
        float cr0 = __expf(m0 - mn0), cr1 = __expf(m1 - mn1);
        m0 = mn0; m1 = mn1;

        float s0 = 0.f, s1 = 0.f;
#pragma unroll
        for (int nj = 0; nj < 8; nj++) {
#pragma unroll
            for (int e = 0; e < 4; e++) {
                float p = __expf(accs[nj][e] - ((e < 2) ? m0 : m1));
                accs[nj][e] = p;
                if (e < 2) s0 += p; else s1 += p;
            }
        }
        s0 += __shfl_xor_sync(0xffffffffu, s0, 1);
        s0 += __shfl_xor_sync(0xffffffffu, s0, 2);
        s1 += __shfl_xor_sync(0xffffffffu, s1, 1);
        s1 += __shfl_xor_sync(0xffffffffu, s1, 2);
        l0 = l0 * cr0 + s0;
        l1 = l1 * cr1 + s1;

#pragma unroll
        for (int nd = 0; nd < 16; nd++) {
            acc_o[nd][0] *= cr0; acc_o[nd][1] *= cr0;
            acc_o[nd][2] *= cr1; acc_o[nd][3] *= cr1;
        }

        cp_wait<0>();
        __syncthreads();

#pragma unroll
        for (int kc2 = 0; kc2 < 4; kc2++) {
            float* p0 = accs[2 * kc2];
            float* p1 = accs[2 * kc2 + 1];
            uint32_t ah[4], al[4];
            ah[0] = pk_f16x2(p0[0], p0[1]);
            ah[1] = pk_f16x2(p0[2], p0[3]);
            ah[2] = pk_f16x2(p1[0], p1[1]);
            ah[3] = pk_f16x2(p1[2], p1[3]);
            {
                float2 f;
                f = unpk_f16x2(ah[0]); al[0] = pk_f16x2(p0[0] - f.x, p0[1] - f.y);
                f = unpk_f16x2(ah[1]); al[1] = pk_f16x2(p0[2] - f.x, p0[3] - f.y);
                f = unpk_f16x2(ah[2]); al[2] = pk_f16x2(p1[0] - f.x, p1[1] - f.y);
                f = unpk_f16x2(ah[3]); al[3] = pk_f16x2(p1[2] - f.x, p1[3] - f.y);
            }
            int vr = kc2 * 16 + v_half * 8 + v_row7;
#pragma unroll
            for (int ndp = 0; ndp < 8; ndp++) {
                int chunk = ndp * 2 + v_sel;
                uint32_t off = (uint32_t)vr * 256u + (uint32_t)((chunk ^ (vr & 7)) * 16);
                uint32_t bh4[4];
                ldmatrix_x4_trans(bh4, sb + 49152u + off);
                mma_16816(acc_o[2 * ndp],     ah, bh4);
                mma_16816(acc_o[2 * ndp],     al, bh4);
                mma_16816(acc_o[2 * ndp + 1], ah, bh4 + 2);
                mma_16816(acc_o[2 * ndp + 1], al, bh4 + 2);
            }
        }
    }

    float inv0 = 1.f / l0, inv1 = 1.f / l1;
    int row0 = b * S_ + qt * 64 + warp * 16 + tg;
#pragma unroll
    for (int nd = 0; nd < 16; nd++) {
        int col = h * HD + nd * 8 + 2 * tc;
        float x0 = acc_o[nd][0] * inv0, x1 = acc_o[nd][1] * inv0;
        float x2 = acc_o[nd][2] * inv1, x3 = acc_o[nd][3] * inv1;
        __half h0 = __float2half_rn(x0), h1 = __float2half_rn(x1);
        __half h2 = __float2half_rn(x2), h3 = __float2half_rn(x3);
        __half e0 = __float2half_rn(x0 - __half2float(h0));
        __half e1 = __float2half_rn(x1 - __half2float(h1));
        __half e2 = __float2half_rn(x2 - __half2float(h2));
        __half e3 = __float2half_rn(x3 - __half2float(h3));
        *(__half2*)(Obf + (size_t)row0 * K2 + col)              = __halves2half2(h0, h1);
        *(__half2*)(Obf + (size_t)row0 * K2 + 4096 + col)       = __halves2half2(e0, e1);
        *(__half2*)(Obf + (size_t)(row0 + 8) * K2 + col)        = __halves2half2(h2, h3);
        *(__half2*)(Obf + (size_t)(row0 + 8) * K2 + 4096 + col) = __halves2half2(e2, e3);
    }
}

// =====================  launch  =============================================
extern "C" void kernel_launch(void* const* d_in, const int* in_sizes, int n_in,
                              void* d_out, int out_size)
{
    const float* x     = (const float*)d_in[0];
    const float* amask = (const float*)d_in[1];
    const int*   pos   = (const int*)  d_in[2];
    const float* wq    = (const float*)d_in[3];
    const float* wk    = (const float*)d_in[4];
    const float* wv    = (const float*)d_in[5];
    const float* wo    = (const float*)d_in[6];
    float* out = (float*)d_out;

    __half *abf, *obf, *wbf;
    cudaGetSymbolAddress((void**)&abf, g_Abf);
    cudaGetSymbolAddress((void**)&obf, g_Obf);
    cudaGetSymbolAddress((void**)&wbf, g_Wbf);

    __half* wqkv_h = wbf;                              // rows [0,6144)
    __half* wo_h   = wbf + (size_t)QKVN * KW;          // rows [0,4096)

    // buffer layout inside g_Abf
    const size_t XSZ = (size_t)MTOK * K2;     // 32M halves: x split
    const size_t QSZ = (size_t)MTOK * D_;     // 16M
    const size_t KSZ = (size_t)MTOK * KVDIM;  // 4M
    __half* xs = abf;
    __half* qh = abf + XSZ;
    __half* ql = qh + QSZ;
    __half* kh = ql + QSZ;
    __half* vh = kh + KSZ;

    cudaFuncSetAttribute(gemm_f16_kernel<1>, cudaFuncAttributeMaxDynamicSharedMemorySize, GEMM_SMEM);
    cudaFuncSetAttribute(gemm_f16_kernel<0>, cudaFuncAttributeMaxDynamicSharedMemorySize, GEMM_SMEM);
    cudaFuncSetAttribute(flash_mma_kernel, cudaFuncAttributeMaxDynamicSharedMemorySize, FL_SMEM);

    // ---- multi-stream fork: weight conversions run on a side stream ----
    cudaStream_t s1;
    cudaStreamCreateWithFlags(&s1, cudaStreamNonBlocking);
    cudaEvent_t evFork, evWqkv, evWo;
    cudaEventCreateWithFlags(&evFork, cudaEventDisableTiming);
    cudaEventCreateWithFlags(&evWqkv, cudaEventDisableTiming);
    cudaEventCreateWithFlags(&evWo,   cudaEventDisableTiming);

    cudaEventRecord(evFork, 0);
    cudaStreamWaitEvent(s1, evFork, 0);

    // side stream: weight conversions
    convert_w_kernel<<<dim3(D_ / 32,    D_ / 32), dim3(32, 8), 0, s1>>>(wq, wqkv_h, D_);
    convert_w_kernel<<<dim3(KVDIM / 32, D_ / 32), dim3(32, 8), 0, s1>>>(wk, wqkv_h + (size_t)4096 * KW, KVDIM);
    convert_w_kernel<<<dim3(KVDIM / 32, D_ / 32), dim3(32, 8), 0, s1>>>(wv, wqkv_h + (size_t)5120 * KW, KVDIM);
    cudaEventRecord(evWqkv, s1);
    convert_w_kernel<<<dim3(D_ / 32,    D_ / 32), dim3(32, 8), 0, s1>>>(wo, wo_h, D_);
    cudaEventRecord(evWo, s1);

    // main stream: rope table + activation split (QKV critical path)
    rope_table_kernel<<<(2048 * 64) / 256, 256>>>();
    convert_a_kernel<<<(MTOK * D_ / 4) / 256, 256>>>(x, xs);

    // join: QKV GEMM needs wq/wk/wv conversions
    cudaStreamWaitEvent(0, evWqkv, 0);

    // Fused QKV projection + rope + scale + fp16 split (one GEMM, N=6144)
    gemm_f16_kernel<1><<<dim3(MTOK / 128, QKVN / 128), 256, GEMM_SMEM>>>(
        xs, wqkv_h, nullptr, QKVN, qh, ql, kh, vh, pos);

    // Attention (tensor-core flash) -> writes split fp16 out-proj operand
    flash_mma_kernel<<<dim3(S_ / 64, NH, B_), 128, FL_SMEM>>>(qh, ql, kh, vh, amask, obf);

    // join: out-proj needs wo conversion (overlapped with GEMM/flash above)
    cudaStreamWaitEvent(0, evWo, 0);

    // Output projection (2-term split A, fp32 out)
    gemm_f16_kernel<0><<<dim3(MTOK / 128, D_ / 128), 256, GEMM_SMEM>>>(
        obf, wo_h, out, D_, nullptr, nullptr, nullptr, nullptr, nullptr);
}